// round 11
// baseline (speedup 1.0000x reference)
#include <cuda_runtime.h>
#include <math.h>

#define BN    64
#define N1P   8192
#define NV    778
#define NFC   1538
#define NP    204

#define GR    8
#define NCELL 512                  // 8^3
#define CS    0.0125f
#define INVCS 80.0f

#define TPB   128
// tickets: [0,64) build, [64,128) normals, [128,256) chamfer (b,dir),
//          [256,768) main (b = m>>3, q = m&7; 1024 points per tile)
#define T_NORM   64
#define T_CHAM   128
#define T_MAINS  256
#define NTILE_MAIN 512
#define NTILES   768
#define NBLOCKS  (148 * 8)         // 1184

__device__ float4 g_opay[BN][N1P];     // sorted obj: (x,y,z,a2)
__device__ int    g_rstart[BN][513];
__device__ float4 g_rpay[BN][NV];      // (-2x,-2y,-2z,b2) sorted by cell
__device__ int    g_ridx[BN][NV];
__device__ int    g_gstart[BN][513];
__device__ float4 g_gpay[BN][NV];
__device__ int    g_pstart[BN][513];
__device__ float4 g_ppay[BN][NP];
__device__ float  g_vn[BN * 3 * NV];
__device__ float  g_part_main[NTILE_MAIN * 5];
__device__ float  g_part_cham[128];
__device__ int    g_ticket = 0;
__device__ int    g_fin = 0;
__device__ int    g_bdone[BN];
__device__ int    g_ndone[BN];

__constant__ int c_prior[NP] = {
697,698,699,700,712,713,714,715,737,738,739,740,741,743,744,745,746,748,749,750,
753,754,755,756,757,758,759,760,761,762,763,764,765,766,767,768,
46,47,48,49,164,165,166,167,194,195,223,237,238,280,281,298,301,317,320,323,
324,325,326,327,328,329,330,331,332,333,340,341,342,343,344,345,346,347,348,349,
350,351,352,353,354,355,
356,357,358,359,375,376,386,387,396,397,402,403,413,429,433,434,435,436,437,438,
439,440,441,442,443,444,452,453,454,455,456,459,460,461,462,463,464,465,466,467,
468,469,470,471,484,485,486,496,497,506,507,513,514,524,545,546,547,548,549,550,
551,552,553,555,563,564,565,566,567,570,572,573,574,575,576,577,578,
580,581,582,583,600,601,602,614,615,624,625,630,631,641,663,664,665,666,667,668,
670,672,680,681,682,683,684,686,687,688,689,690,691,692,693,694,695,
73,96,98,99,772,774,775,777};

__device__ __forceinline__ int cell_of(float x) {
    int c = (int)(x * INVCS);
    return c < 0 ? 0 : (c > GR - 1 ? GR - 1 : c);
}

// exclusive scan of cnt[512] -> writes gout[0..512], leaves cnt[c]=start_c
__device__ void scan512(int* cnt, int* wsum, int tid, int* gout) {
    const int base = tid * 4;
    int l0 = cnt[base], l1 = cnt[base+1], l2 = cnt[base+2], l3 = cnt[base+3];
    int p1 = l0, p2 = l0 + l1, p3 = l0 + l1 + l2, s = p3 + l3;
    const unsigned lane = tid & 31, w = tid >> 5;
    int v = s;
    for (int o = 1; o < 32; o <<= 1) {
        int t = __shfl_up_sync(0xFFFFFFFFu, v, o);
        if (lane >= o) v += t;
    }
    if (lane == 31) wsum[w] = v;
    __syncthreads();
    int carry = 0;
    for (int i = 0; i < (int)w; i++) carry += wsum[i];
    int tb = v - s + carry;
    cnt[base] = tb; cnt[base+1] = tb + p1; cnt[base+2] = tb + p2; cnt[base+3] = tb + p3;
    gout[base] = tb; gout[base+1] = tb + p1; gout[base+2] = tb + p2; gout[base+3] = tb + p3;
    if (tid == TPB - 1) gout[512] = tb + s;
    __syncthreads();
}

__global__ __launch_bounds__(TPB, 8) void k_mega(const float* __restrict__ obj,
                                                 const float* __restrict__ recon,
                                                 const float* __restrict__ gt,
                                                 const int* __restrict__ faces,
                                                 const float* __restrict__ mean,
                                                 const float* __restrict__ logv,
                                                 const float* __restrict__ rp,
                                                 const float* __restrict__ xp,
                                                 float* __restrict__ out) {
    __shared__ __align__(16) float S[6 * NV];   // 18.7KB union scratch
    __shared__ float s_red[20];
    __shared__ int   s_tile;
    const int tid = threadIdx.x;

    while (true) {
        __syncthreads();
        if (tid == 0) s_tile = atomicAdd(&g_ticket, 1);
        __syncthreads();
        const int tile = s_tile;
        if (tile >= NTILES) break;

        if (tile < T_NORM) {
            // ================= build tile (batch b): 4 grids =================
            const int b = tile;
            int* cnt  = (int*)S;
            int* wsum = (int*)S + NCELL;

            // ---- recon grid ----
            for (int i = tid; i < NCELL; i += TPB) cnt[i] = 0;
            __syncthreads();
            const float* rb = recon + (size_t)b * NV * 3;
            for (int v = tid; v < NV; v += TPB) {
                int c = (cell_of(rb[3*v+2]) * GR + cell_of(rb[3*v+1])) * GR + cell_of(rb[3*v+0]);
                atomicAdd(&cnt[c], 1);
            }
            __syncthreads();
            scan512(cnt, wsum, tid, g_rstart[b]);
            for (int v = tid; v < NV; v += TPB) {
                float x = rb[3*v+0], y = rb[3*v+1], z = rb[3*v+2];
                int c = (cell_of(z) * GR + cell_of(y)) * GR + cell_of(x);
                int pos = atomicAdd(&cnt[c], 1);
                g_rpay[b][pos] = make_float4(-2.f*x, -2.f*y, -2.f*z,
                                             fmaf(z, z, fmaf(y, y, x*x)));
                g_ridx[b][pos] = v;
            }
            __syncthreads();

            // ---- gt grid ----
            for (int i = tid; i < NCELL; i += TPB) cnt[i] = 0;
            __syncthreads();
            const float* gb = gt + (size_t)b * NV * 3;
            for (int v = tid; v < NV; v += TPB) {
                int c = (cell_of(gb[3*v+2]) * GR + cell_of(gb[3*v+1])) * GR + cell_of(gb[3*v+0]);
                atomicAdd(&cnt[c], 1);
            }
            __syncthreads();
            scan512(cnt, wsum, tid, g_gstart[b]);
            for (int v = tid; v < NV; v += TPB) {
                float x = gb[3*v+0], y = gb[3*v+1], z = gb[3*v+2];
                int c = (cell_of(z) * GR + cell_of(y)) * GR + cell_of(x);
                int pos = atomicAdd(&cnt[c], 1);
                g_gpay[b][pos] = make_float4(-2.f*x, -2.f*y, -2.f*z,
                                             fmaf(z, z, fmaf(y, y, x*x)));
            }
            __syncthreads();

            // ---- prior grid ----
            for (int i = tid; i < NCELL; i += TPB) cnt[i] = 0;
            __syncthreads();
            for (int i = tid; i < NP; i += TPB) {
                int v = c_prior[i];
                int c = (cell_of(rb[3*v+2]) * GR + cell_of(rb[3*v+1])) * GR + cell_of(rb[3*v+0]);
                atomicAdd(&cnt[c], 1);
            }
            __syncthreads();
            scan512(cnt, wsum, tid, g_pstart[b]);
            for (int i = tid; i < NP; i += TPB) {
                int v = c_prior[i];
                float x = rb[3*v+0], y = rb[3*v+1], z = rb[3*v+2];
                int c = (cell_of(z) * GR + cell_of(y)) * GR + cell_of(x);
                int pos = atomicAdd(&cnt[c], 1);
                g_ppay[b][pos] = make_float4(-2.f*x, -2.f*y, -2.f*z,
                                             fmaf(z, z, fmaf(y, y, x*x)));
            }
            __syncthreads();

            // ---- obj sort ----
            for (int i = tid; i < NCELL; i += TPB) cnt[i] = 0;
            __syncthreads();
            const float* ob = obj + (size_t)b * N1P * 3;
            for (int v = tid; v < N1P; v += TPB) {
                int c = (cell_of(ob[3*v+2]) * GR + cell_of(ob[3*v+1])) * GR + cell_of(ob[3*v+0]);
                atomicAdd(&cnt[c], 1);
            }
            __syncthreads();
            // scan in place (no global starts needed for obj)
            {
                int* dummy = (int*)&g_opay[b][0];  // unused target slot is fine? NO — write real:
                // use g_rstart? must not clobber. Use a local path: replicate scan without gout.
                (void)dummy;
            }
            // inline scan without global output
            {
                const int base = tid * 4;
                int l0 = cnt[base], l1 = cnt[base+1], l2 = cnt[base+2], l3 = cnt[base+3];
                int p1 = l0, p2 = l0 + l1, p3 = l0 + l1 + l2, sm = p3 + l3;
                const unsigned lane = tid & 31, w = tid >> 5;
                int v = sm;
                for (int o = 1; o < 32; o <<= 1) {
                    int t = __shfl_up_sync(0xFFFFFFFFu, v, o);
                    if (lane >= o) v += t;
                }
                if (lane == 31) wsum[w] = v;
                __syncthreads();
                int carry = 0;
                for (int i = 0; i < (int)w; i++) carry += wsum[i];
                int tb = v - sm + carry;
                cnt[base] = tb; cnt[base+1] = tb + p1; cnt[base+2] = tb + p2; cnt[base+3] = tb + p3;
                __syncthreads();
            }
            for (int v = tid; v < N1P; v += TPB) {
                float x = ob[3*v+0], y = ob[3*v+1], z = ob[3*v+2];
                int c = (cell_of(z) * GR + cell_of(y)) * GR + cell_of(x);
                int pos = atomicAdd(&cnt[c], 1);
                g_opay[b][pos] = make_float4(x, y, z, fmaf(z, z, fmaf(y, y, x*x)));
            }
            __syncthreads();
            __threadfence();
            if (tid == 0) atomicExch(&g_bdone[b], 1);
        }
        else if (tile < T_CHAM) {
            // ================= normals tile =================
            const int b = tile - T_NORM;
            float* sx = S;          float* sy = S + NV;      float* sz = S + 2 * NV;
            float* nx = S + 3 * NV; float* ny = S + 4 * NV;  float* nz = S + 5 * NV;
            const float* rb = recon + (size_t)b * NV * 3;
            for (int v = tid; v < NV; v += TPB) {
                sx[v] = rb[3*v+0]; sy[v] = rb[3*v+1]; sz[v] = rb[3*v+2];
                nx[v] = 0.f; ny[v] = 0.f; nz[v] = 0.f;
            }
            __syncthreads();
            for (int f = tid; f < NFC; f += TPB) {
                int i0 = faces[3*f+0], i1 = faces[3*f+1], i2 = faces[3*f+2];
                float e1x = sx[i1]-sx[i0], e1y = sy[i1]-sy[i0], e1z = sz[i1]-sz[i0];
                float e2x = sx[i2]-sx[i0], e2y = sy[i2]-sy[i0], e2z = sz[i2]-sz[i0];
                float fx = e1y*e2z - e1z*e2y;
                float fy = e1z*e2x - e1x*e2z;
                float fz = e1x*e2y - e1y*e2x;
                atomicAdd(&nx[i0], fx); atomicAdd(&ny[i0], fy); atomicAdd(&nz[i0], fz);
                atomicAdd(&nx[i1], fx); atomicAdd(&ny[i1], fy); atomicAdd(&nz[i1], fz);
                atomicAdd(&nx[i2], fx); atomicAdd(&ny[i2], fy); atomicAdd(&nz[i2], fz);
            }
            __syncthreads();
            float* vb = g_vn + (size_t)b * 3 * NV;
            for (int v = tid; v < NV; v += TPB) {
                float x = nx[v], y = ny[v], z = nz[v];
                float inv = 1.f / (sqrtf(x*x + y*y + z*z) + 1e-12f);
                vb[v] = x*inv; vb[NV+v] = y*inv; vb[2*NV+v] = z*inv;
            }
            __syncthreads();
            __threadfence();
            if (tid == 0) atomicExch(&g_ndone[b], 1);
        }
        else if (tile < T_MAINS) {
            // ================= chamfer tile (grid ring search) =================
            const int c   = tile - T_CHAM;
            const int b   = c >> 1;
            const int dir = c & 1;          // 0: recon->gt, 1: gt->recon
            if (tid == 0) { while (((volatile int*)g_bdone)[b] == 0) { } }
            __syncthreads();
            __threadfence();
            const float4* spy = dir ? g_gpay[b]   : g_rpay[b];
            const int*    tst = dir ? g_rstart[b] : g_gstart[b];
            const float4* tpy = dir ? g_rpay[b]   : g_gpay[b];

            float part = 0.f;
            for (int rnd = 0; rnd < 7; rnd++) {
                const int r = rnd * TPB + tid;
                const bool ok = (r < NV);
                float4 Ps = ok ? __ldg(spy + r) : make_float4(0.f, 0.f, 0.f, 0.f);
                float ax = -0.5f * Ps.x, ay = -0.5f * Ps.y, az = -0.5f * Ps.z, a2 = Ps.w;
                const unsigned FULL = 0xFFFFFFFFu;
                float ax0 = __shfl_sync(FULL, ax, 0);
                float ay0 = __shfl_sync(FULL, ay, 0);
                float az0 = __shfl_sync(FULL, az, 0);
                if (!ok) { ax = ax0; ay = ay0; az = az0; a2 = 0.f; }
                int cx = cell_of(ax), cy = cell_of(ay), cz = cell_of(az);
                int bx0 = (int)__reduce_min_sync(FULL, (unsigned)cx);
                int bx1 = (int)__reduce_max_sync(FULL, (unsigned)cx);
                int by0 = (int)__reduce_min_sync(FULL, (unsigned)cy);
                int by1 = (int)__reduce_max_sync(FULL, (unsigned)cy);
                int bz0 = (int)__reduce_min_sync(FULL, (unsigned)cz);
                int bz1 = (int)__reduce_max_sync(FULL, (unsigned)cz);
                float bC = ok ? 3e38f : -3e38f;
                for (int k = 0; k < GR; k++) {
                    int x0 = max(0, bx0-k), x1 = min(GR-1, bx1+k);
                    int y0 = max(0, by0-k), y1 = min(GR-1, by1+k);
                    int z0 = max(0, bz0-k), z1 = min(GR-1, bz1+k);
                    for (int z = z0; z <= z1; z++)
                    for (int y = y0; y <= y1; y++)
                    for (int x = x0; x <= x1; x++) {
                        if (k > 0 && x >= bx0-(k-1) && x <= bx1+(k-1)
                                  && y >= by0-(k-1) && y <= by1+(k-1)
                                  && z >= bz0-(k-1) && z <= bz1+(k-1)) continue;
                        int cid = (z * GR + y) * GR + x;
                        int t0 = __ldg(tst + cid), t1 = __ldg(tst + cid + 1);
                        for (int j = t0; j < t1; j++) {
                            float4 T = __ldg(tpy + j);
                            float d = fmaf(az, T.z, fmaf(ay, T.y, fmaf(ax, T.x, T.w)));
                            bC = fminf(bC, d);
                        }
                    }
                    if (k >= 1) {
                        float bd = ((float)k * CS) * ((float)k * CS);
                        if (__all_sync(FULL, bC + a2 <= bd)) break;
                    }
                }
                if (ok) part += fmaxf(bC + a2, 0.f);
            }
            for (int off = 16; off; off >>= 1) part += __shfl_down_sync(0xFFFFFFFFu, part, off);
            if ((tid & 31) == 0) s_red[tid >> 5] = part;
            __syncthreads();
            if (tid == 0)
                g_part_cham[c] = s_red[0] + s_red[1] + s_red[2] + s_red[3];
        }
        else {
            // ================= main tile (grid ring search) =================
            const int m = tile - T_MAINS;
            const int b = m >> 3;
            const int q = m & 7;
            if (tid == 0) {
                while (((volatile int*)g_bdone)[b] == 0) { }
                while (((volatile int*)g_ndone)[b] == 0) { }
            }
            __syncthreads();
            __threadfence();

            const int*    rst = g_rstart[b];
            const float4* rpy = g_rpay[b];
            const int*    rix = g_ridx[b];
            const int*    gst = g_gstart[b];
            const float4* gpy = g_gpay[b];
            const int*    pst = g_pstart[b];
            const float4* ppy = g_ppay[b];
            const float*  vb  = g_vn + (size_t)b * 3 * NV;
            const float*  rbase = recon + (size_t)b * NV * 3;

            float cm = 0.f, pen = 0.f, npn = 0.f, cons = 0.f, gtc = 0.f;
            for (int rnd = 0; rnd < 8; rnd++) {
                const int pi = q * 1024 + rnd * TPB + tid;
                float4 P = g_opay[b][pi];
                const float ax = P.x, ay = P.y, az = P.z, a2 = P.w;
                int cx = cell_of(ax), cy = cell_of(ay), cz = cell_of(az);
                const unsigned FULL = 0xFFFFFFFFu;
                int bx0 = (int)__reduce_min_sync(FULL, (unsigned)cx);
                int bx1 = (int)__reduce_max_sync(FULL, (unsigned)cx);
                int by0 = (int)__reduce_min_sync(FULL, (unsigned)cy);
                int by1 = (int)__reduce_max_sync(FULL, (unsigned)cy);
                int bz0 = (int)__reduce_min_sync(FULL, (unsigned)cz);
                int bz1 = (int)__reduce_max_sync(FULL, (unsigned)cz);

                float bR = 3e38f, bG = 3e38f, bP = 3e38f;
                int biR = 0;
                for (int k = 0; k < GR; k++) {
                    int x0 = max(0, bx0-k), x1 = min(GR-1, bx1+k);
                    int y0 = max(0, by0-k), y1 = min(GR-1, by1+k);
                    int z0 = max(0, bz0-k), z1 = min(GR-1, bz1+k);
                    for (int z = z0; z <= z1; z++)
                    for (int y = y0; y <= y1; y++)
                    for (int x = x0; x <= x1; x++) {
                        if (k > 0 && x >= bx0-(k-1) && x <= bx1+(k-1)
                                  && y >= by0-(k-1) && y <= by1+(k-1)
                                  && z >= bz0-(k-1) && z <= bz1+(k-1)) continue;
                        int cid = (z * GR + y) * GR + x;
                        int r0 = __ldg(rst + cid), r1 = __ldg(rst + cid + 1);
                        for (int j = r0; j < r1; j++) {
                            float4 T = __ldg(rpy + j);
                            float d = fmaf(az, T.z, fmaf(ay, T.y, fmaf(ax, T.x, T.w)));
                            if (d < bR) { bR = d; biR = j; }
                        }
                        int g0 = __ldg(gst + cid), g1 = __ldg(gst + cid + 1);
                        for (int j = g0; j < g1; j++) {
                            float4 T = __ldg(gpy + j);
                            float d = fmaf(az, T.z, fmaf(ay, T.y, fmaf(ax, T.x, T.w)));
                            bG = fminf(bG, d);
                        }
                        int p0 = __ldg(pst + cid), p1 = __ldg(pst + cid + 1);
                        for (int j = p0; j < p1; j++) {
                            float4 T = __ldg(ppy + j);
                            float d = fmaf(az, T.z, fmaf(ay, T.y, fmaf(ax, T.x, T.w)));
                            bP = fminf(bP, d);
                        }
                    }
                    if (k >= 1) {
                        float bd = ((float)k * CS) * ((float)k * CS);
                        bool done = (bR + a2 <= bd) && (bP + a2 <= bd);
                        if (__all_sync(FULL, done)) break;
                    }
                }
                float drec = fmaxf(bR + a2, 0.f);
                float dg   = fmaxf(bG + a2, 0.f);
                float dpr  = fmaxf(bP + a2, 0.f);
                if (drec < 1e-4f) { cm += dpr; npn += 1.f; }
                bool rc = sqrtf(drec) < 0.005f;
                bool gc = sqrtf(dg)   < 0.005f;
                if (gc) { gtc += 1.f; if (rc) cons += 1.f; }
                int idx = __ldg(rix + biR);
                const float* rv = rbase + (size_t)idx * 3;
                float dot = (__ldg(rv)     - ax) * __ldg(vb + idx)
                          + (__ldg(rv + 1) - ay) * __ldg(vb + NV + idx)
                          + (__ldg(rv + 2) - az) * __ldg(vb + 2 * NV + idx);
                if (dot > 0.f) pen += drec;
            }

            for (int off = 16; off; off >>= 1) {
                cm   += __shfl_down_sync(0xFFFFFFFFu, cm,   off);
                pen  += __shfl_down_sync(0xFFFFFFFFu, pen,  off);
                npn  += __shfl_down_sync(0xFFFFFFFFu, npn,  off);
                cons += __shfl_down_sync(0xFFFFFFFFu, cons, off);
                gtc  += __shfl_down_sync(0xFFFFFFFFu, gtc,  off);
            }
            const int wid = tid >> 5, lane = tid & 31;
            if (lane == 0) {
                s_red[wid]      = cm;   s_red[4 + wid]  = pen;
                s_red[8 + wid]  = npn;  s_red[12 + wid] = cons;
                s_red[16 + wid] = gtc;
            }
            __syncthreads();
            if (tid == 0) {
                float cc = 0, p = 0, n = 0, co = 0, g = 0;
                for (int w = 0; w < 4; w++) {
                    cc += s_red[w]; p += s_red[4+w]; n += s_red[8+w];
                    co += s_red[12+w]; g += s_red[16+w];
                }
                float* gp = g_part_main + (size_t)m * 5;
                gp[0] = cc; gp[1] = p; gp[2] = n; gp[3] = co; gp[4] = g;
            }
        }
    }

    // ================= finale: last block combines =================
    __syncthreads();
    if (tid == 0) {
        __threadfence();
        int r = atomicAdd(&g_fin, 1);
        s_tile = (r == NBLOCKS - 1) ? 1 : 0;
    }
    __syncthreads();
    if (s_tile) {
        __threadfence();
        float sp = 0.f, sk = 0.f, sc = 0.f;
        float scm = 0.f, spe = 0.f, snp = 0.f, sco = 0.f, sgt = 0.f;
        for (int i = tid; i < BN * 61; i += TPB) { float d = rp[i] - xp[i]; sp += d * d; }
        for (int i = tid; i < BN * 64; i += TPB) {
            float mm = mean[i], lv = logv[i];
            sk += 1.f + lv - mm*mm - expf(lv);
        }
        for (int i = tid; i < 128; i += TPB) sc += g_part_cham[i];
        for (int i = tid; i < NTILE_MAIN; i += TPB) {
            const float* gp = g_part_main + (size_t)i * 5;
            scm += gp[0]; spe += gp[1]; snp += gp[2]; sco += gp[3]; sgt += gp[4];
        }
        for (int off = 16; off; off >>= 1) {
            sp  += __shfl_down_sync(0xFFFFFFFFu, sp,  off);
            sk  += __shfl_down_sync(0xFFFFFFFFu, sk,  off);
            sc  += __shfl_down_sync(0xFFFFFFFFu, sc,  off);
            scm += __shfl_down_sync(0xFFFFFFFFu, scm, off);
            spe += __shfl_down_sync(0xFFFFFFFFu, spe, off);
            snp += __shfl_down_sync(0xFFFFFFFFu, snp, off);
            sco += __shfl_down_sync(0xFFFFFFFFu, sco, off);
            sgt += __shfl_down_sync(0xFFFFFFFFu, sgt, off);
        }
        const int wid = tid >> 5;
        if ((tid & 31) == 0) {
            s_red[wid]      = sp;  s_red[4 + wid]  = sk;
            s_red[8 + wid]  = sc;  s_red[12 + wid] = scm;
            S[wid] = spe; S[4 + wid] = snp; S[8 + wid] = sco; S[12 + wid] = sgt;
        }
        __syncthreads();
        if (tid == 0) {
            float t0=0,t1=0,t2=0,t3=0,t4=0,t5=0,t6=0,t7=0;
            for (int w = 0; w < 4; w++) {
                t0 += s_red[w]; t1 += s_red[4+w]; t2 += s_red[8+w]; t3 += s_red[12+w];
                t4 += S[w];     t5 += S[4+w];     t6 += S[8+w];     t7 += S[12+w];
            }
            double param_loss  = (double)t0 / 64.0;
            double KLD         = -0.5 * (double)t1 / 64.0 * 10.0;
            double recon_loss  = (double)t2 / 64.0;
            double cmap_loss   = 3000.0 * (double)t3 / (64.0 * (double)t5);
            double consistency = -5.0 * (double)t6 / ((double)t7 + 0.0001);
            double penetr      = 100.0 * (double)t4 / 64.0;
            double loss = (recon_loss + KLD) + 0.1 * param_loss
                        + 1000.0 * cmap_loss + 10.0 * consistency + 10.0 * penetr;
            out[0] = (float)loss;
        }
        // reset for deterministic graph replay
        for (int i = tid; i < BN; i += TPB) { g_bdone[i] = 0; g_ndone[i] = 0; }
        __syncthreads();
        if (tid == 0) { g_ticket = 0; g_fin = 0; __threadfence(); }
    }
}

extern "C" void kernel_launch(void* const* d_in, const int* in_sizes, int n_in,
                              void* d_out, int out_size) {
    const float* obj   = (const float*)d_in[0];
    const float* recon = (const float*)d_in[1];
    const float* gt    = (const float*)d_in[2];
    const float* mean  = (const float*)d_in[3];
    const float* logv  = (const float*)d_in[4];
    const float* rp    = (const float*)d_in[5];
    const float* xp    = (const float*)d_in[6];
    const int*   faces = (const int*)d_in[7];
    float* out = (float*)d_out;

    k_mega<<<NBLOCKS, TPB>>>(obj, recon, gt, faces, mean, logv, rp, xp, out);
}

// round 12
// speedup vs baseline: 8.1043x; 8.1043x over previous
#include <cuda_runtime.h>
#include <math.h>

#define BN   64
#define N1P  8192
#define NV   778
#define VP   780      // padded to multiple of 4
#define NFC  1538
#define NP   204      // prior subset size

#define PTS        4
#define TPB        128
#define MAIN_GX    16                      // 16 main tiles per batch
#define NTILE_MAIN (MAIN_GX * BN)          // 1024
#define NTILE_CHAM (2 * BN)                // 128
// tickets: 0 = slot-map, [1,65) normals, [65,1089) main, [1089,1217) chamfer
#define T_NORM     1
#define T_MAIN     (T_NORM + BN)           // 65
#define T_CHAM     (T_MAIN + NTILE_MAIN)   // 1089
#define NTILES     (T_CHAM + NTILE_CHAM)   // 1217
#define NBLOCKS    (148 * 6)               // 888, all co-resident at 6 blocks/SM

__device__ float g_vn[BN * 3 * NV];
__device__ float g_part_main[NTILE_MAIN * 5];
__device__ float g_part_cham[NTILE_CHAM];
__device__ int   g_slot2orig[VP];
__device__ int   g_ticket = 0;
__device__ int   g_done = 0;
__device__ int   g_mapdone = 0;
__device__ int   g_fin = 0;

// PRIOR_IDX sorted ascending (204 entries)
__constant__ int c_prior_sorted[NP] = {
46,47,48,49,73,96,98,99,
164,165,166,167,194,195,223,237,238,280,281,298,301,317,320,
323,324,325,326,327,328,329,330,331,332,333,
340,341,342,343,344,345,346,347,348,349,350,351,352,353,354,355,
356,357,358,359,375,376,386,387,396,397,402,403,413,429,
433,434,435,436,437,438,439,440,441,442,443,444,
452,453,454,455,456,459,460,461,462,463,464,465,466,467,
468,469,470,471,484,485,486,496,497,506,507,513,514,524,
545,546,547,548,549,550,551,552,553,555,
563,564,565,566,567,570,572,573,574,575,576,577,578,
580,581,582,583,600,601,602,614,615,624,625,630,631,641,
663,664,665,666,667,668,670,672,
680,681,682,683,684,686,687,688,689,690,691,692,693,694,695,
697,698,699,700,712,713,714,715,
737,738,739,740,741,743,744,745,746,748,749,750,
753,754,755,756,757,758,759,760,761,762,763,764,765,766,767,768,
772,774,775,777};

typedef unsigned long long u64;

__device__ __forceinline__ u64 ffma2(u64 a, u64 b, u64 c) {
    u64 d;
    asm("fma.rn.f32x2 %0, %1, %2, %3;" : "=l"(d) : "l"(a), "l"(b), "l"(c));
    return d;
}
__device__ __forceinline__ u64 bcast2(float x) {
    u64 r;
    asm("mov.b64 %0, {%1, %2};" : "=l"(r) : "f"(x), "f"(x));
    return r;
}
__device__ __forceinline__ void unpack2f(u64 v, float& lo, float& hi) {
    asm("mov.b64 {%0, %1}, %2;" : "=f"(lo), "=f"(hi) : "l"(v));
}

__global__ __launch_bounds__(TPB, 6) void k_mega(const float* __restrict__ obj,
                                                 const float* __restrict__ recon,
                                                 const float* __restrict__ gt,
                                                 const int* __restrict__ faces,
                                                 const float* __restrict__ mean,
                                                 const float* __restrict__ logv,
                                                 const float* __restrict__ rp,
                                                 const float* __restrict__ xp,
                                                 float* __restrict__ out) {
    __shared__ __align__(16) float S[8 * VP];   // 24.96KB
    __shared__ float s_red[20];
    __shared__ int   s_tile;
    const int tid = threadIdx.x;

    while (true) {
        __syncthreads();
        if (tid == 0) s_tile = atomicAdd(&g_ticket, 1);
        __syncthreads();
        const int tile = s_tile;
        if (tile >= NTILES) break;

        if (tile == 0) {
            // ---------------- slot-map build ----------------
            for (int j = tid; j < NV; j += TPB) {
                int lo = 0, hi = NP;
                while (lo < hi) { int mid = (lo + hi) >> 1;
                    if (c_prior_sorted[mid] < j) lo = mid + 1; else hi = mid; }
                bool member = (lo < NP) && (c_prior_sorted[lo] == j);
                int slot = member ? lo : (NP + j - lo);
                g_slot2orig[slot] = j;
            }
            for (int s = NV + tid; s < VP; s += TPB) g_slot2orig[s] = -1;
            __syncthreads();
            __threadfence();
            if (tid == 0) atomicExch(&g_mapdone, 1);
        }
        else if (tile < T_MAIN) {
            // ---------------- normals tile ----------------
            const int b = tile - T_NORM;
            float* sx = S;          float* sy = S + NV;      float* sz = S + 2 * NV;
            float* nx = S + 3 * NV; float* ny = S + 4 * NV;  float* nz = S + 5 * NV;
            const float* rb = recon + (size_t)b * NV * 3;
            for (int v = tid; v < NV; v += TPB) {
                sx[v] = rb[3*v+0]; sy[v] = rb[3*v+1]; sz[v] = rb[3*v+2];
                nx[v] = 0.f; ny[v] = 0.f; nz[v] = 0.f;
            }
            __syncthreads();
            for (int f = tid; f < NFC; f += TPB) {
                int i0 = faces[3*f+0], i1 = faces[3*f+1], i2 = faces[3*f+2];
                float e1x = sx[i1]-sx[i0], e1y = sy[i1]-sy[i0], e1z = sz[i1]-sz[i0];
                float e2x = sx[i2]-sx[i0], e2y = sy[i2]-sy[i0], e2z = sz[i2]-sz[i0];
                float fx = e1y*e2z - e1z*e2y;
                float fy = e1z*e2x - e1x*e2z;
                float fz = e1x*e2y - e1y*e2x;
                atomicAdd(&nx[i0], fx); atomicAdd(&ny[i0], fy); atomicAdd(&nz[i0], fz);
                atomicAdd(&nx[i1], fx); atomicAdd(&ny[i1], fy); atomicAdd(&nz[i1], fz);
                atomicAdd(&nx[i2], fx); atomicAdd(&ny[i2], fy); atomicAdd(&nz[i2], fz);
            }
            __syncthreads();
            float* vb = g_vn + (size_t)b * 3 * NV;
            for (int v = tid; v < NV; v += TPB) {
                float x = nx[v], y = ny[v], z = nz[v];
                float inv = 1.f / (sqrtf(x*x + y*y + z*z) + 1e-12f);
                vb[v] = x*inv; vb[NV+v] = y*inv; vb[2*NV+v] = z*inv;
            }
            __syncthreads();
            __threadfence();
            if (tid == 0) atomicAdd(&g_done, 1);
        }
        else if (tile < T_CHAM) {
            // ---------------- main tile ----------------
            const int m  = tile - T_MAIN;
            const int b  = m >> 4;
            const int xt = m & 15;
            float* rmx = S;          float* rmy = S + VP;   float* rmz = S + 2*VP; float* rcc = S + 3*VP;
            float* tmx = S + 4*VP;   float* tmy = S + 5*VP; float* tmz = S + 6*VP; float* tcc = S + 7*VP;

            if (tid == 0) { while (*(volatile int*)&g_mapdone == 0) { } }
            __syncthreads();
            __threadfence();

            const float* rb = recon + (size_t)b * NV * 3;
            const float* gb = gt    + (size_t)b * NV * 3;
            for (int v = tid; v < VP; v += TPB) {
                int orig = g_slot2orig[v];
                if (orig >= 0) {
                    float x = rb[3*orig+0], y = rb[3*orig+1], z = rb[3*orig+2];
                    rmx[v] = -2.f*x; rmy[v] = -2.f*y; rmz[v] = -2.f*z;
                    rcc[v] = fmaf(z, z, fmaf(y, y, x*x));
                } else {
                    rmx[v]=0.f; rmy[v]=0.f; rmz[v]=0.f; rcc[v]=3e37f;
                }
                if (v < NV) {
                    float x = gb[3*v+0], y = gb[3*v+1], z = gb[3*v+2];
                    tmx[v] = -2.f*x; tmy[v] = -2.f*y; tmz[v] = -2.f*z;
                    tcc[v] = fmaf(z, z, fmaf(y, y, x*x));
                } else {
                    tmx[v]=0.f; tmy[v]=0.f; tmz[v]=0.f; tcc[v]=3e37f;
                }
            }
            __syncthreads();

            // broadcast-packed coords only (scalars recovered in epilogue by unpack)
            u64 AX[PTS], AY[PTS], AZ[PTS];
            {
                const int base = xt * (TPB * PTS) + tid;
                #pragma unroll
                for (int i = 0; i < PTS; i++) {
                    const float* o = obj + ((size_t)b * N1P + base + i * TPB) * 3;
                    AX[i] = bcast2(o[0]); AY[i] = bcast2(o[1]); AZ[i] = bcast2(o[2]);
                }
            }

            float dgt[PTS], mA[PTS], mr[PTS];
            int   bt[PTS];
            #pragma unroll
            for (int i = 0; i < PTS; i++) {
                dgt[i] = 3e38f; mA[i] = 3e38f; mr[i] = 3e38f; bt[i] = 0;
            }

            // gt sweep (tree-min)
            #pragma unroll 2
            for (int t = 0; t < VP; t += 4) {
                ulonglong2 X = *(const ulonglong2*)(tmx + t);
                ulonglong2 Y = *(const ulonglong2*)(tmy + t);
                ulonglong2 Z = *(const ulonglong2*)(tmz + t);
                ulonglong2 C = *(const ulonglong2*)(tcc + t);
                #pragma unroll
                for (int i = 0; i < PTS; i++) {
                    u64 d2 = ffma2(AZ[i], Z.x, ffma2(AY[i], Y.x, ffma2(AX[i], X.x, C.x)));
                    float lo1, hi1; unpack2f(d2, lo1, hi1);
                    d2 = ffma2(AZ[i], Z.y, ffma2(AY[i], Y.y, ffma2(AX[i], X.y, C.y)));
                    float lo2, hi2; unpack2f(d2, lo2, hi2);
                    dgt[i] = fminf(dgt[i], fminf(fminf(lo1, hi1), fminf(lo2, hi2)));
                }
            }

            // recon sweep, segment A: prior slots [0,204) — also tracks prior min
            #pragma unroll 2
            for (int t = 0; t < NP; t += 4) {
                ulonglong2 X = *(const ulonglong2*)(rmx + t);
                ulonglong2 Y = *(const ulonglong2*)(rmy + t);
                ulonglong2 Z = *(const ulonglong2*)(rmz + t);
                ulonglong2 C = *(const ulonglong2*)(rcc + t);
                #pragma unroll
                for (int i = 0; i < PTS; i++) {
                    u64 d2 = ffma2(AZ[i], Z.x, ffma2(AY[i], Y.x, ffma2(AX[i], X.x, C.x)));
                    float lo1, hi1; unpack2f(d2, lo1, hi1);
                    d2 = ffma2(AZ[i], Z.y, ffma2(AY[i], Y.y, ffma2(AX[i], X.y, C.y)));
                    float lo2, hi2; unpack2f(d2, lo2, hi2);
                    float h = fminf(fminf(lo1, hi1), fminf(lo2, hi2));
                    mA[i] = fminf(mA[i], h);
                    bool c = h < mr[i];
                    mr[i] = fminf(mr[i], h);
                    bt[i] = c ? t : bt[i];
                }
            }
            // segment B: slots [204,VP)
            #pragma unroll 2
            for (int t = NP; t < VP; t += 4) {
                ulonglong2 X = *(const ulonglong2*)(rmx + t);
                ulonglong2 Y = *(const ulonglong2*)(rmy + t);
                ulonglong2 Z = *(const ulonglong2*)(rmz + t);
                ulonglong2 C = *(const ulonglong2*)(rcc + t);
                #pragma unroll
                for (int i = 0; i < PTS; i++) {
                    u64 d2 = ffma2(AZ[i], Z.x, ffma2(AY[i], Y.x, ffma2(AX[i], X.x, C.x)));
                    float lo1, hi1; unpack2f(d2, lo1, hi1);
                    d2 = ffma2(AZ[i], Z.y, ffma2(AY[i], Y.y, ffma2(AX[i], X.y, C.y)));
                    float lo2, hi2; unpack2f(d2, lo2, hi2);
                    float h = fminf(fminf(lo1, hi1), fminf(lo2, hi2));
                    bool c = h < mr[i];
                    mr[i] = fminf(mr[i], h);
                    bt[i] = c ? t : bt[i];
                }
            }

            if (tid == 0) { while (*(volatile int*)&g_done < BN) { } }
            __syncthreads();
            __threadfence();

            float cm = 0.f, pen = 0.f, npn = 0.f, cons = 0.f, gtc = 0.f;
            const float* vb = g_vn + (size_t)b * 3 * NV;
            #pragma unroll
            for (int i = 0; i < PTS; i++) {
                float ax_, ay_, az_, junk;
                unpack2f(AX[i], ax_, junk);
                unpack2f(AY[i], ay_, junk);
                unpack2f(AZ[i], az_, junk);
                const float a2 = fmaf(az_, az_, fmaf(ay_, ay_, ax_ * ax_));
                const int t = bt[i];
                const float m2 = mr[i];
                int slot = t;
                #pragma unroll
                for (int jj = 3; jj >= 0; jj--) {   // reverse scan: earliest slot wins
                    int j = t + jj;
                    float dj = fmaf(az_, rmz[j], fmaf(ay_, rmy[j], fmaf(ax_, rmx[j], rcc[j])));
                    if (dj == m2) slot = j;
                }
                const int idx = g_slot2orig[slot];
                float drec = fmaxf(m2 + a2, 0.f);
                float dg   = fmaxf(dgt[i] + a2, 0.f);
                float dpr  = fmaxf(mA[i] + a2, 0.f);
                if (drec < 1e-4f) { cm += dpr; npn += 1.f; }
                bool rc = sqrtf(drec) < 0.005f;
                bool gc = sqrtf(dg)   < 0.005f;
                if (gc) { gtc += 1.f; if (rc) cons += 1.f; }
                float nvx = -0.5f * rmx[slot], nvy = -0.5f * rmy[slot], nvz = -0.5f * rmz[slot];
                float dot = (nvx - ax_) * __ldcg(vb + idx)
                          + (nvy - ay_) * __ldcg(vb + NV + idx)
                          + (nvz - az_) * __ldcg(vb + 2 * NV + idx);
                if (dot > 0.f) pen += drec;
            }

            for (int off = 16; off; off >>= 1) {
                cm   += __shfl_down_sync(0xFFFFFFFFu, cm,   off);
                pen  += __shfl_down_sync(0xFFFFFFFFu, pen,  off);
                npn  += __shfl_down_sync(0xFFFFFFFFu, npn,  off);
                cons += __shfl_down_sync(0xFFFFFFFFu, cons, off);
                gtc  += __shfl_down_sync(0xFFFFFFFFu, gtc,  off);
            }
            const int wid = tid >> 5, lane = tid & 31;
            if (lane == 0) {
                s_red[wid]      = cm;   s_red[4 + wid]  = pen;
                s_red[8 + wid]  = npn;  s_red[12 + wid] = cons;
                s_red[16 + wid] = gtc;
            }
            __syncthreads();
            if (tid == 0) {
                float c = 0, p = 0, n = 0, co = 0, g = 0;
                for (int w = 0; w < 4; w++) {
                    c += s_red[w]; p += s_red[4+w]; n += s_red[8+w];
                    co += s_red[12+w]; g += s_red[16+w];
                }
                float* gp = g_part_main + (size_t)m * 5;
                gp[0] = c; gp[1] = p; gp[2] = n; gp[3] = co; gp[4] = g;
            }
        }
        else {
            // ---------------- chamfer tile: dir per block ----------------
            const int c   = tile - T_CHAM;       // 0..127
            const int b   = c >> 1;
            const int dir = c & 1;
            const float* srcp = (dir ? gt : recon) + (size_t)b * NV * 3;
            const float* tgtp = (dir ? recon : gt) + (size_t)b * NV * 3;
            float* tmx = S;        float* tmy = S + VP;
            float* tmz = S + 2*VP; float* tcc = S + 3*VP;
            for (int v = tid; v < VP; v += TPB) {
                if (v < NV) {
                    float x = tgtp[3*v+0], y = tgtp[3*v+1], z = tgtp[3*v+2];
                    tmx[v] = -2.f*x; tmy[v] = -2.f*y; tmz[v] = -2.f*z;
                    tcc[v] = fmaf(z, z, fmaf(y, y, x*x));
                } else { tmx[v]=0.f; tmy[v]=0.f; tmz[v]=0.f; tcc[v]=3e37f; }
            }
            __syncthreads();

            const int CROWS = 7;
            u64 CAX[CROWS], CAY[CROWS], CAZ[CROWS];
            float ca2[CROWS];
            bool  cok[CROWS];
            #pragma unroll
            for (int s = 0; s < CROWS; s++) {
                int r = tid + s * TPB;
                cok[s] = (r < NV);
                float x = 0.f, y = 0.f, z = 0.f;
                if (cok[s]) { x = srcp[3*r+0]; y = srcp[3*r+1]; z = srcp[3*r+2]; }
                ca2[s] = fmaf(z, z, fmaf(y, y, x*x));
                CAX[s] = bcast2(x); CAY[s] = bcast2(y); CAZ[s] = bcast2(z);
            }
            float cm0[CROWS];
            #pragma unroll
            for (int s = 0; s < CROWS; s++) cm0[s] = 3e38f;

            #pragma unroll 1
            for (int t = 0; t < VP; t += 4) {
                ulonglong2 X = *(const ulonglong2*)(tmx + t);
                ulonglong2 Y = *(const ulonglong2*)(tmy + t);
                ulonglong2 Z = *(const ulonglong2*)(tmz + t);
                ulonglong2 C = *(const ulonglong2*)(tcc + t);
                #pragma unroll
                for (int s = 0; s < CROWS; s++) {
                    u64 d2 = ffma2(CAZ[s], Z.x, ffma2(CAY[s], Y.x, ffma2(CAX[s], X.x, C.x)));
                    float lo1, hi1; unpack2f(d2, lo1, hi1);
                    d2 = ffma2(CAZ[s], Z.y, ffma2(CAY[s], Y.y, ffma2(CAX[s], X.y, C.y)));
                    float lo2, hi2; unpack2f(d2, lo2, hi2);
                    cm0[s] = fminf(cm0[s], fminf(fminf(lo1, hi1), fminf(lo2, hi2)));
                }
            }
            float part = 0.f;
            #pragma unroll
            for (int s = 0; s < CROWS; s++)
                if (cok[s]) part += fmaxf(cm0[s] + ca2[s], 0.f);

            for (int off = 16; off; off >>= 1) part += __shfl_down_sync(0xFFFFFFFFu, part, off);
            if ((tid & 31) == 0) s_red[tid >> 5] = part;
            __syncthreads();
            if (tid == 0)
                g_part_cham[c] = s_red[0] + s_red[1] + s_red[2] + s_red[3];
        }
    }

    // ---------------- completion: last block does final combine ----------------
    __syncthreads();
    if (tid == 0) {
        __threadfence();
        int r = atomicAdd(&g_fin, 1);
        s_tile = (r == NBLOCKS - 1) ? 1 : 0;
    }
    __syncthreads();
    if (s_tile) {
        __threadfence();
        float sp = 0.f, sk = 0.f, sc = 0.f;
        float scm = 0.f, spe = 0.f, snp = 0.f, sco = 0.f, sgt = 0.f;
        for (int i = tid; i < BN * 61; i += TPB) { float d = rp[i] - xp[i]; sp += d * d; }
        for (int i = tid; i < BN * 64; i += TPB) {
            float m = mean[i], lv = logv[i];
            sk += 1.f + lv - m*m - expf(lv);
        }
        for (int i = tid; i < NTILE_CHAM; i += TPB) sc += g_part_cham[i];
        for (int i = tid; i < NTILE_MAIN; i += TPB) {
            const float* gp = g_part_main + (size_t)i * 5;
            scm += gp[0]; spe += gp[1]; snp += gp[2]; sco += gp[3]; sgt += gp[4];
        }
        for (int off = 16; off; off >>= 1) {
            sp  += __shfl_down_sync(0xFFFFFFFFu, sp,  off);
            sk  += __shfl_down_sync(0xFFFFFFFFu, sk,  off);
            sc  += __shfl_down_sync(0xFFFFFFFFu, sc,  off);
            scm += __shfl_down_sync(0xFFFFFFFFu, scm, off);
            spe += __shfl_down_sync(0xFFFFFFFFu, spe, off);
            snp += __shfl_down_sync(0xFFFFFFFFu, snp, off);
            sco += __shfl_down_sync(0xFFFFFFFFu, sco, off);
            sgt += __shfl_down_sync(0xFFFFFFFFu, sgt, off);
        }
        const int wid = tid >> 5;
        if ((tid & 31) == 0) {
            s_red[wid]      = sp;  s_red[4 + wid]  = sk;
            s_red[8 + wid]  = sc;  s_red[12 + wid] = scm;
            S[wid] = spe; S[4 + wid] = snp; S[8 + wid] = sco; S[12 + wid] = sgt;
        }
        __syncthreads();
        if (tid == 0) {
            float t0=0,t1=0,t2=0,t3=0,t4=0,t5=0,t6=0,t7=0;
            for (int w = 0; w < 4; w++) {
                t0 += s_red[w]; t1 += s_red[4+w]; t2 += s_red[8+w]; t3 += s_red[12+w];
                t4 += S[w];     t5 += S[4+w];     t6 += S[8+w];     t7 += S[12+w];
            }
            double param_loss  = (double)t0 / 64.0;
            double KLD         = -0.5 * (double)t1 / 64.0 * 10.0;
            double recon_loss  = (double)t2 / 64.0;
            double cmap_loss   = 3000.0 * (double)t3 / (64.0 * (double)t5);
            double consistency = -5.0 * (double)t6 / ((double)t7 + 0.0001);
            double penetr      = 100.0 * (double)t4 / 64.0;
            double loss = (recon_loss + KLD) + 0.1 * param_loss
                        + 1000.0 * cmap_loss + 10.0 * consistency + 10.0 * penetr;
            out[0] = (float)loss;
            g_ticket = 0; g_done = 0; g_mapdone = 0; g_fin = 0;
            __threadfence();
        }
    }
}

extern "C" void kernel_launch(void* const* d_in, const int* in_sizes, int n_in,
                              void* d_out, int out_size) {
    const float* obj   = (const float*)d_in[0];
    const float* recon = (const float*)d_in[1];
    const float* gt    = (const float*)d_in[2];
    const float* mean  = (const float*)d_in[3];
    const float* logv  = (const float*)d_in[4];
    const float* rp    = (const float*)d_in[5];
    const float* xp    = (const float*)d_in[6];
    const int*   faces = (const int*)d_in[7];
    float* out = (float*)d_out;

    k_mega<<<NBLOCKS, TPB>>>(obj, recon, gt, faces, mean, logv, rp, xp, out);
}

// round 14
// speedup vs baseline: 10.2621x; 1.2663x over previous
#include <cuda_runtime.h>
#include <math.h>

#define BN   64
#define N1P  8192
#define NV   778
#define VP   780      // padded to multiple of 4
#define NFC  1538
#define NP   204      // prior subset size

#define PTS        4
#define TPB        128
#define MAIN_GX    16                      // 16 main tiles per batch
#define NTILE_MAIN (MAIN_GX * BN)          // 1024
#define NTILE_CHAM (2 * BN)                // 128
// tickets: 0 = slot-map, [1,65) normals+gtsort, [65,1089) main, [1089,1217) chamfer
#define T_NORM     1
#define T_MAIN     (T_NORM + BN)           // 65
#define T_CHAM     (T_MAIN + NTILE_MAIN)   // 1089
#define NTILES     (T_CHAM + NTILE_CHAM)   // 1217
#define NBLOCKS    (148 * 4)               // 592 — best measured residency

#define GC         4                       // gt grid 4^3
#define GCELLS     64
#define GCS        0.025f
#define GINV       40.0f
#define GTHR       2.5e-5f                 // 0.005^2
#define GRAD       0.005f

__device__ float  g_vn[BN * 3 * NV];
__device__ float4 g_gsrt[BN][NV];          // gt sorted by cell: (-2x,-2y,-2z,b2)
__device__ int    g_gstart[BN][GCELLS + 1];
__device__ float  g_part_main[NTILE_MAIN * 5];
__device__ float  g_part_cham[NTILE_CHAM];
__device__ int    g_slot2orig[VP];
__device__ int    g_ticket = 0;
__device__ int    g_ndone[BN];             // normals + gt-sort complete per batch
__device__ int    g_mapdone = 0;
__device__ int    g_fin = 0;

// PRIOR_IDX sorted ascending (204 entries)
__constant__ int c_prior_sorted[NP] = {
46,47,48,49,73,96,98,99,
164,165,166,167,194,195,223,237,238,280,281,298,301,317,320,
323,324,325,326,327,328,329,330,331,332,333,
340,341,342,343,344,345,346,347,348,349,350,351,352,353,354,355,
356,357,358,359,375,376,386,387,396,397,402,403,413,429,
433,434,435,436,437,438,439,440,441,442,443,444,
452,453,454,455,456,459,460,461,462,463,464,465,466,467,
468,469,470,471,484,485,486,496,497,506,507,513,514,524,
545,546,547,548,549,550,551,552,553,555,
563,564,565,566,567,570,572,573,574,575,576,577,578,
580,581,582,583,600,601,602,614,615,624,625,630,631,641,
663,664,665,666,667,668,670,672,
680,681,682,683,684,686,687,688,689,690,691,692,693,694,695,
697,698,699,700,712,713,714,715,
737,738,739,740,741,743,744,745,746,748,749,750,
753,754,755,756,757,758,759,760,761,762,763,764,765,766,767,768,
772,774,775,777};

typedef unsigned long long u64;

__device__ __forceinline__ u64 ffma2(u64 a, u64 b, u64 c) {
    u64 d;
    asm("fma.rn.f32x2 %0, %1, %2, %3;" : "=l"(d) : "l"(a), "l"(b), "l"(c));
    return d;
}
__device__ __forceinline__ u64 bcast2(float x) {
    u64 r;
    asm("mov.b64 %0, {%1, %2};" : "=l"(r) : "f"(x), "f"(x));
    return r;
}
__device__ __forceinline__ void unpack2f(u64 v, float& lo, float& hi) {
    asm("mov.b64 {%0, %1}, %2;" : "=f"(lo), "=f"(hi) : "l"(v));
}
__device__ __forceinline__ int cell4(float v) {
    int c = (int)(v * GINV);
    return c < 0 ? 0 : (c > GC - 1 ? GC - 1 : c);
}

__global__ __launch_bounds__(TPB, 4) void k_mega(const float* __restrict__ obj,
                                                 const float* __restrict__ recon,
                                                 const float* __restrict__ gt,
                                                 const int* __restrict__ faces,
                                                 const float* __restrict__ mean,
                                                 const float* __restrict__ logv,
                                                 const float* __restrict__ rp,
                                                 const float* __restrict__ xp,
                                                 float* __restrict__ out) {
    // union scratch: max(normals 6*NV, main 4*VP + NV float4 + 66 ints) ≈ 25.3KB
    __shared__ __align__(16) float S[4 * VP + 4 * NV + 80];
    __shared__ float s_red[20];
    __shared__ int   s_tile;
    const int tid = threadIdx.x;

    while (true) {
        __syncthreads();
        if (tid == 0) s_tile = atomicAdd(&g_ticket, 1);
        __syncthreads();
        const int tile = s_tile;
        if (tile >= NTILES) break;

        if (tile == 0) {
            // ---------------- slot-map build ----------------
            for (int j = tid; j < NV; j += TPB) {
                int lo = 0, hi = NP;
                while (lo < hi) { int mid = (lo + hi) >> 1;
                    if (c_prior_sorted[mid] < j) lo = mid + 1; else hi = mid; }
                bool member = (lo < NP) && (c_prior_sorted[lo] == j);
                int slot = member ? lo : (NP + j - lo);
                g_slot2orig[slot] = j;
            }
            for (int s = NV + tid; s < VP; s += TPB) g_slot2orig[s] = -1;
            __syncthreads();
            __threadfence();
            if (tid == 0) atomicExch(&g_mapdone, 1);
        }
        else if (tile < T_MAIN) {
            // ---------------- normals + gt counting sort (batch b) ----------------
            const int b = tile - T_NORM;
            float* sx = S;          float* sy = S + NV;      float* sz = S + 2 * NV;
            float* nx = S + 3 * NV; float* ny = S + 4 * NV;  float* nz = S + 5 * NV;
            const float* rb = recon + (size_t)b * NV * 3;
            for (int v = tid; v < NV; v += TPB) {
                sx[v] = rb[3*v+0]; sy[v] = rb[3*v+1]; sz[v] = rb[3*v+2];
                nx[v] = 0.f; ny[v] = 0.f; nz[v] = 0.f;
            }
            __syncthreads();
            for (int f = tid; f < NFC; f += TPB) {
                int i0 = faces[3*f+0], i1 = faces[3*f+1], i2 = faces[3*f+2];
                float e1x = sx[i1]-sx[i0], e1y = sy[i1]-sy[i0], e1z = sz[i1]-sz[i0];
                float e2x = sx[i2]-sx[i0], e2y = sy[i2]-sy[i0], e2z = sz[i2]-sz[i0];
                float fx = e1y*e2z - e1z*e2y;
                float fy = e1z*e2x - e1x*e2z;
                float fz = e1x*e2y - e1y*e2x;
                atomicAdd(&nx[i0], fx); atomicAdd(&ny[i0], fy); atomicAdd(&nz[i0], fz);
                atomicAdd(&nx[i1], fx); atomicAdd(&ny[i1], fy); atomicAdd(&nz[i1], fz);
                atomicAdd(&nx[i2], fx); atomicAdd(&ny[i2], fy); atomicAdd(&nz[i2], fz);
            }
            __syncthreads();
            float* vb = g_vn + (size_t)b * 3 * NV;
            for (int v = tid; v < NV; v += TPB) {
                float x = nx[v], y = ny[v], z = nz[v];
                float inv = 1.f / (sqrtf(x*x + y*y + z*z) + 1e-12f);
                vb[v] = x*inv; vb[NV+v] = y*inv; vb[2*NV+v] = z*inv;
            }
            __syncthreads();

            // ---- gt counting sort into 4^3 grid ----
            int* cnt = (int*)S;
            for (int i = tid; i < GCELLS; i += TPB) cnt[i] = 0;
            __syncthreads();
            const float* gb = gt + (size_t)b * NV * 3;
            for (int v = tid; v < NV; v += TPB) {
                int c = (cell4(gb[3*v+2]) * GC + cell4(gb[3*v+1])) * GC + cell4(gb[3*v+0]);
                atomicAdd(&cnt[c], 1);
            }
            __syncthreads();
            if (tid == 0) {
                int run = 0;
                for (int c = 0; c < GCELLS; c++) {
                    int t = cnt[c]; cnt[c] = run; g_gstart[b][c] = run; run += t;
                }
                g_gstart[b][GCELLS] = run;
            }
            __syncthreads();
            for (int v = tid; v < NV; v += TPB) {
                float x = gb[3*v+0], y = gb[3*v+1], z = gb[3*v+2];
                int c = (cell4(z) * GC + cell4(y)) * GC + cell4(x);
                int pos = atomicAdd(&cnt[c], 1);
                g_gsrt[b][pos] = make_float4(-2.f*x, -2.f*y, -2.f*z,
                                             fmaf(z, z, fmaf(y, y, x*x)));
            }
            __syncthreads();
            __threadfence();
            if (tid == 0) atomicExch(&g_ndone[b], 1);
        }
        else if (tile < T_CHAM) {
            // ---------------- main tile ----------------
            const int m  = tile - T_MAIN;
            const int b  = m >> 4;
            const int xt = m & 15;
            float*  rmx  = S;        float* rmy = S + VP;
            float*  rmz  = S + 2*VP; float* rcc = S + 3*VP;
            float4* sgt  = (float4*)(S + 4 * VP);       // NV float4
            int*    sgst = (int*)(S + 4 * VP + 4 * NV); // 65 ints

            if (tid == 0) {
                while (*(volatile int*)&g_mapdone == 0) { }
                while (((volatile int*)g_ndone)[b] == 0) { }
            }
            __syncthreads();
            __threadfence();

            const float* rb = recon + (size_t)b * NV * 3;
            for (int v = tid; v < VP; v += TPB) {
                int orig = g_slot2orig[v];
                if (orig >= 0) {
                    float x = rb[3*orig+0], y = rb[3*orig+1], z = rb[3*orig+2];
                    rmx[v] = -2.f*x; rmy[v] = -2.f*y; rmz[v] = -2.f*z;
                    rcc[v] = fmaf(z, z, fmaf(y, y, x*x));
                } else {
                    rmx[v]=0.f; rmy[v]=0.f; rmz[v]=0.f; rcc[v]=3e37f;
                }
            }
            for (int v = tid; v < NV; v += TPB) sgt[v] = __ldg(&g_gsrt[b][v]);
            for (int i = tid; i < GCELLS + 1; i += TPB) sgst[i] = g_gstart[b][i];
            __syncthreads();

            u64 AX[PTS], AY[PTS], AZ[PTS];
            {
                const int base = xt * (TPB * PTS) + tid;
                #pragma unroll
                for (int i = 0; i < PTS; i++) {
                    const float* o = obj + ((size_t)b * N1P + base + i * TPB) * 3;
                    AX[i] = bcast2(o[0]); AY[i] = bcast2(o[1]); AZ[i] = bcast2(o[2]);
                }
            }

            float mA[PTS], mr[PTS];
            int   bt[PTS];
            #pragma unroll
            for (int i = 0; i < PTS; i++) { mA[i] = 3e38f; mr[i] = 3e38f; bt[i] = 0; }

            // recon sweep, segment A: prior slots [0,204) — also tracks prior min
            #pragma unroll 2
            for (int t = 0; t < NP; t += 4) {
                ulonglong2 X = *(const ulonglong2*)(rmx + t);
                ulonglong2 Y = *(const ulonglong2*)(rmy + t);
                ulonglong2 Z = *(const ulonglong2*)(rmz + t);
                ulonglong2 C = *(const ulonglong2*)(rcc + t);
                #pragma unroll
                for (int i = 0; i < PTS; i++) {
                    u64 d2 = ffma2(AZ[i], Z.x, ffma2(AY[i], Y.x, ffma2(AX[i], X.x, C.x)));
                    float lo1, hi1; unpack2f(d2, lo1, hi1);
                    d2 = ffma2(AZ[i], Z.y, ffma2(AY[i], Y.y, ffma2(AX[i], X.y, C.y)));
                    float lo2, hi2; unpack2f(d2, lo2, hi2);
                    float h = fminf(fminf(lo1, hi1), fminf(lo2, hi2));
                    mA[i] = fminf(mA[i], h);
                    bool c = h < mr[i];
                    mr[i] = fminf(mr[i], h);
                    bt[i] = c ? t : bt[i];
                }
            }
            // segment B: slots [204,VP)
            #pragma unroll 2
            for (int t = NP; t < VP; t += 4) {
                ulonglong2 X = *(const ulonglong2*)(rmx + t);
                ulonglong2 Y = *(const ulonglong2*)(rmy + t);
                ulonglong2 Z = *(const ulonglong2*)(rmz + t);
                ulonglong2 C = *(const ulonglong2*)(rcc + t);
                #pragma unroll
                for (int i = 0; i < PTS; i++) {
                    u64 d2 = ffma2(AZ[i], Z.x, ffma2(AY[i], Y.x, ffma2(AX[i], X.x, C.x)));
                    float lo1, hi1; unpack2f(d2, lo1, hi1);
                    d2 = ffma2(AZ[i], Z.y, ffma2(AY[i], Y.y, ffma2(AX[i], X.y, C.y)));
                    float lo2, hi2; unpack2f(d2, lo2, hi2);
                    float h = fminf(fminf(lo1, hi1), fminf(lo2, hi2));
                    bool c = h < mr[i];
                    mr[i] = fminf(mr[i], h);
                    bt[i] = c ? t : bt[i];
                }
            }

            float cm = 0.f, pen = 0.f, npn = 0.f, cons = 0.f, gtc = 0.f;
            const float* vb = g_vn + (size_t)b * 3 * NV;
            #pragma unroll
            for (int i = 0; i < PTS; i++) {
                float ax_, ay_, az_, junk;
                unpack2f(AX[i], ax_, junk);
                unpack2f(AY[i], ay_, junk);
                unpack2f(AZ[i], az_, junk);
                const float a2 = fmaf(az_, az_, fmaf(ay_, ay_, ax_ * ax_));

                // ---- gt boolean via grid scan of the ±0.005 cube ----
                bool gc = false;
                {
                    int x0 = cell4(ax_ - GRAD), x1 = cell4(ax_ + GRAD);
                    int y0 = cell4(ay_ - GRAD), y1 = cell4(ay_ + GRAD);
                    int z0 = cell4(az_ - GRAD), z1 = cell4(az_ + GRAD);
                    for (int zz = z0; zz <= z1; zz++)
                    for (int yy = y0; yy <= y1; yy++)
                    for (int xx = x0; xx <= x1; xx++) {
                        int c = (zz * GC + yy) * GC + xx;
                        int s0 = sgst[c], s1 = sgst[c + 1];
                        for (int j = s0; j < s1; j++) {
                            float4 T = sgt[j];
                            float d = fmaf(az_, T.z, fmaf(ay_, T.y, fmaf(ax_, T.x, T.w)));
                            gc |= (d + a2 < GTHR);
                        }
                    }
                }

                // exact argmin recovery (earliest slot wins within winning group)
                const int t = bt[i];
                const float m2 = mr[i];
                int slot = t;
                #pragma unroll
                for (int jj = 3; jj >= 0; jj--) {
                    int j = t + jj;
                    float dj = fmaf(az_, rmz[j], fmaf(ay_, rmy[j], fmaf(ax_, rmx[j], rcc[j])));
                    if (dj == m2) slot = j;
                }
                const int idx = g_slot2orig[slot];
                float drec = fmaxf(m2 + a2, 0.f);
                float dpr  = fmaxf(mA[i] + a2, 0.f);
                if (drec < 1e-4f) { cm += dpr; npn += 1.f; }
                bool rc = sqrtf(drec) < 0.005f;
                if (gc) { gtc += 1.f; if (rc) cons += 1.f; }
                float nvx = -0.5f * rmx[slot], nvy = -0.5f * rmy[slot], nvz = -0.5f * rmz[slot];
                float dot = (nvx - ax_) * __ldcg(vb + idx)
                          + (nvy - ay_) * __ldcg(vb + NV + idx)
                          + (nvz - az_) * __ldcg(vb + 2 * NV + idx);
                if (dot > 0.f) pen += drec;
            }

            for (int off = 16; off; off >>= 1) {
                cm   += __shfl_down_sync(0xFFFFFFFFu, cm,   off);
                pen  += __shfl_down_sync(0xFFFFFFFFu, pen,  off);
                npn  += __shfl_down_sync(0xFFFFFFFFu, npn,  off);
                cons += __shfl_down_sync(0xFFFFFFFFu, cons, off);
                gtc  += __shfl_down_sync(0xFFFFFFFFu, gtc,  off);
            }
            const int wid = tid >> 5, lane = tid & 31;
            if (lane == 0) {
                s_red[wid]      = cm;   s_red[4 + wid]  = pen;
                s_red[8 + wid]  = npn;  s_red[12 + wid] = cons;
                s_red[16 + wid] = gtc;
            }
            __syncthreads();
            if (tid == 0) {
                float c = 0, p = 0, n = 0, co = 0, g = 0;
                for (int w = 0; w < 4; w++) {
                    c += s_red[w]; p += s_red[4+w]; n += s_red[8+w];
                    co += s_red[12+w]; g += s_red[16+w];
                }
                float* gp = g_part_main + (size_t)m * 5;
                gp[0] = c; gp[1] = p; gp[2] = n; gp[3] = co; gp[4] = g;
            }
        }
        else {
            // ---------------- chamfer tile (brute, unchanged) ----------------
            const int c   = tile - T_CHAM;       // 0..127
            const int b   = c >> 1;
            const int dir = c & 1;
            const float* srcp = (dir ? gt : recon) + (size_t)b * NV * 3;
            const float* tgtp = (dir ? recon : gt) + (size_t)b * NV * 3;
            float* tmx = S;        float* tmy = S + VP;
            float* tmz = S + 2*VP; float* tcc = S + 3*VP;
            for (int v = tid; v < VP; v += TPB) {
                if (v < NV) {
                    float x = tgtp[3*v+0], y = tgtp[3*v+1], z = tgtp[3*v+2];
                    tmx[v] = -2.f*x; tmy[v] = -2.f*y; tmz[v] = -2.f*z;
                    tcc[v] = fmaf(z, z, fmaf(y, y, x*x));
                } else { tmx[v]=0.f; tmy[v]=0.f; tmz[v]=0.f; tcc[v]=3e37f; }
            }
            __syncthreads();

            const int CROWS = 7;
            u64 CAX[CROWS], CAY[CROWS], CAZ[CROWS];
            float ca2[CROWS];
            bool  cok[CROWS];
            #pragma unroll
            for (int s = 0; s < CROWS; s++) {
                int r = tid + s * TPB;
                cok[s] = (r < NV);
                float x = 0.f, y = 0.f, z = 0.f;
                if (cok[s]) { x = srcp[3*r+0]; y = srcp[3*r+1]; z = srcp[3*r+2]; }
                ca2[s] = fmaf(z, z, fmaf(y, y, x*x));
                CAX[s] = bcast2(x); CAY[s] = bcast2(y); CAZ[s] = bcast2(z);
            }
            float cm0[CROWS];
            #pragma unroll
            for (int s = 0; s < CROWS; s++) cm0[s] = 3e38f;

            #pragma unroll 1
            for (int t = 0; t < VP; t += 4) {
                ulonglong2 X = *(const ulonglong2*)(tmx + t);
                ulonglong2 Y = *(const ulonglong2*)(tmy + t);
                ulonglong2 Z = *(const ulonglong2*)(tmz + t);
                ulonglong2 C = *(const ulonglong2*)(tcc + t);
                #pragma unroll
                for (int s = 0; s < CROWS; s++) {
                    u64 d2 = ffma2(CAZ[s], Z.x, ffma2(CAY[s], Y.x, ffma2(CAX[s], X.x, C.x)));
                    float lo1, hi1; unpack2f(d2, lo1, hi1);
                    d2 = ffma2(CAZ[s], Z.y, ffma2(CAY[s], Y.y, ffma2(CAX[s], X.y, C.y)));
                    float lo2, hi2; unpack2f(d2, lo2, hi2);
                    cm0[s] = fminf(cm0[s], fminf(fminf(lo1, hi1), fminf(lo2, hi2)));
                }
            }
            float part = 0.f;
            #pragma unroll
            for (int s = 0; s < CROWS; s++)
                if (cok[s]) part += fmaxf(cm0[s] + ca2[s], 0.f);

            for (int off = 16; off; off >>= 1) part += __shfl_down_sync(0xFFFFFFFFu, part, off);
            if ((tid & 31) == 0) s_red[tid >> 5] = part;
            __syncthreads();
            if (tid == 0)
                g_part_cham[c] = s_red[0] + s_red[1] + s_red[2] + s_red[3];
        }
    }

    // ---------------- completion: last block does final combine ----------------
    __syncthreads();
    if (tid == 0) {
        __threadfence();
        int r = atomicAdd(&g_fin, 1);
        s_tile = (r == NBLOCKS - 1) ? 1 : 0;
    }
    __syncthreads();
    if (s_tile) {
        __threadfence();
        float sp = 0.f, sk = 0.f, sc = 0.f;
        float scm = 0.f, spe = 0.f, snp = 0.f, sco = 0.f, sgt2 = 0.f;
        for (int i = tid; i < BN * 61; i += TPB) { float d = rp[i] - xp[i]; sp += d * d; }
        for (int i = tid; i < BN * 64; i += TPB) {
            float m = mean[i], lv = logv[i];
            sk += 1.f + lv - m*m - expf(lv);
        }
        for (int i = tid; i < NTILE_CHAM; i += TPB) sc += g_part_cham[i];
        for (int i = tid; i < NTILE_MAIN; i += TPB) {
            const float* gp = g_part_main + (size_t)i * 5;
            scm += gp[0]; spe += gp[1]; snp += gp[2]; sco += gp[3]; sgt2 += gp[4];
        }
        for (int off = 16; off; off >>= 1) {
            sp   += __shfl_down_sync(0xFFFFFFFFu, sp,   off);
            sk   += __shfl_down_sync(0xFFFFFFFFu, sk,   off);
            sc   += __shfl_down_sync(0xFFFFFFFFu, sc,   off);
            scm  += __shfl_down_sync(0xFFFFFFFFu, scm,  off);
            spe  += __shfl_down_sync(0xFFFFFFFFu, spe,  off);
            snp  += __shfl_down_sync(0xFFFFFFFFu, snp,  off);
            sco  += __shfl_down_sync(0xFFFFFFFFu, sco,  off);
            sgt2 += __shfl_down_sync(0xFFFFFFFFu, sgt2, off);
        }
        const int wid = tid >> 5;
        if ((tid & 31) == 0) {
            s_red[wid]      = sp;  s_red[4 + wid]  = sk;
            s_red[8 + wid]  = sc;  s_red[12 + wid] = scm;
            S[wid] = spe; S[4 + wid] = snp; S[8 + wid] = sco; S[12 + wid] = sgt2;
        }
        __syncthreads();
        if (tid == 0) {
            float t0=0,t1=0,t2=0,t3=0,t4=0,t5=0,t6=0,t7=0;
            for (int w = 0; w < 4; w++) {
                t0 += s_red[w]; t1 += s_red[4+w]; t2 += s_red[8+w]; t3 += s_red[12+w];
                t4 += S[w];     t5 += S[4+w];     t6 += S[8+w];     t7 += S[12+w];
            }
            double param_loss  = (double)t0 / 64.0;
            double KLD         = -0.5 * (double)t1 / 64.0 * 10.0;
            double recon_loss  = (double)t2 / 64.0;
            double cmap_loss   = 3000.0 * (double)t3 / (64.0 * (double)t5);
            double consistency = -5.0 * (double)t6 / ((double)t7 + 0.0001);
            double penetr      = 100.0 * (double)t4 / 64.0;
            double loss = (recon_loss + KLD) + 0.1 * param_loss
                        + 1000.0 * cmap_loss + 10.0 * consistency + 10.0 * penetr;
            out[0] = (float)loss;
        }
        // reset for deterministic graph replay
        for (int i = tid; i < BN; i += TPB) g_ndone[i] = 0;
        __syncthreads();
        if (tid == 0) { g_ticket = 0; g_mapdone = 0; g_fin = 0; __threadfence(); }
    }
}

extern "C" void kernel_launch(void* const* d_in, const int* in_sizes, int n_in,
                              void* d_out, int out_size) {
    const float* obj   = (const float*)d_in[0];
    const float* recon = (const float*)d_in[1];
    const float* gt    = (const float*)d_in[2];
    const float* mean  = (const float*)d_in[3];
    const float* logv  = (const float*)d_in[4];
    const float* rp    = (const float*)d_in[5];
    const float* xp    = (const float*)d_in[6];
    const int*   faces = (const int*)d_in[7];
    float* out = (float*)d_out;

    k_mega<<<NBLOCKS, TPB>>>(obj, recon, gt, faces, mean, logv, rp, xp, out);
}

// round 16
// speedup vs baseline: 10.8892x; 1.0611x over previous
#include <cuda_runtime.h>
#include <math.h>

#define BN   64
#define N1P  8192
#define NV   778
#define VP   780
#define NFC  1538
#define NP   204

#define PTS   4
#define TPB   128
#define MAIN_GX    16
#define NTILE_MAIN (MAIN_GX * BN)          // 1024
#define NTILE_CHAM (2 * BN)                // 128
// tickets: [0,64) build, [64,192) chamfer (no deps), [192,1216) main
#define T_CHAMT    64
#define T_MAINT    192
#define NTILES     (T_MAINT + NTILE_MAIN)  // 1216
#define NBLOCKS    (148 * 4)               // 592

// x-slabs
#define NS     16
#define SW     0.00625f
#define SWINV  160.0f
#define RV2    832                         // padded recon capacity
#define PV2    256                         // padded prior capacity

// gt grid (4^3)
#define GC     4
#define GCELLS 64
#define GINV   40.0f
#define GTHR   2.5e-5f
#define GRAD   0.005f

__device__ float  g_vn[BN * 3 * NV];
__device__ float4 g_osrt[BN][N1P];         // obj sorted by x: (x,y,z,a2)
__device__ float4 g_rsrt[BN][RV2];         // recon slab-sorted: (-2x,-2y,-2z,c)
__device__ int    g_ridx[BN][RV2];
__device__ int    g_rses[BN][NS + 1];      // element starts (multiples of 4)
__device__ float4 g_psrt[BN][PV2];
__device__ int    g_pses[BN][NS + 1];
__device__ float4 g_gsrt[BN][NV];
__device__ int    g_gstart[BN][GCELLS + 1];
__device__ float  g_part_main[NTILE_MAIN * 5];
__device__ float  g_part_cham[NTILE_CHAM];
__device__ int    g_ticket = 0;
__device__ int    g_bdone[BN];
__device__ int    g_fin = 0;

__constant__ int c_prior[NP] = {
697,698,699,700,712,713,714,715,737,738,739,740,741,743,744,745,746,748,749,750,
753,754,755,756,757,758,759,760,761,762,763,764,765,766,767,768,
46,47,48,49,164,165,166,167,194,195,223,237,238,280,281,298,301,317,320,323,
324,325,326,327,328,329,330,331,332,333,340,341,342,343,344,345,346,347,348,349,
350,351,352,353,354,355,
356,357,358,359,375,376,386,387,396,397,402,403,413,429,433,434,435,436,437,438,
439,440,441,442,443,444,452,453,454,455,456,459,460,461,462,463,464,465,466,467,
468,469,470,471,484,485,486,496,497,506,507,513,514,524,545,546,547,548,549,550,
551,552,553,555,563,564,565,566,567,570,572,573,574,575,576,577,578,
580,581,582,583,600,601,602,614,615,624,625,630,631,641,663,664,665,666,667,668,
670,672,680,681,682,683,684,686,687,688,689,690,691,692,693,694,695,
73,96,98,99,772,774,775,777};

typedef unsigned long long u64;

__device__ __forceinline__ u64 ffma2(u64 a, u64 b, u64 c) {
    u64 d;
    asm("fma.rn.f32x2 %0, %1, %2, %3;" : "=l"(d) : "l"(a), "l"(b), "l"(c));
    return d;
}
__device__ __forceinline__ u64 bcast2(float x) {
    u64 r;
    asm("mov.b64 %0, {%1, %2};" : "=l"(r) : "f"(x), "f"(x));
    return r;
}
__device__ __forceinline__ void unpack2f(u64 v, float& lo, float& hi) {
    asm("mov.b64 {%0, %1}, %2;" : "=f"(lo), "=f"(hi) : "l"(v));
}
__device__ __forceinline__ int slab16(float x) {
    int c = (int)(x * SWINV);
    return c < 0 ? 0 : (c > NS - 1 ? NS - 1 : c);
}
__device__ __forceinline__ int cell4(float v) {
    int c = (int)(v * GINV);
    return c < 0 ? 0 : (c > GC - 1 ? GC - 1 : c);
}

// smem layout (floats)
#define O_SRX  0
#define O_SRY  (O_SRX + RV2)
#define O_SRZ  (O_SRY + RV2)
#define O_SRC  (O_SRZ + RV2)
#define O_SIDX (O_SRC + RV2)
#define O_SPX  (O_SIDX + RV2)
#define O_SPY  (O_SPX + PV2)
#define O_SPZ  (O_SPY + PV2)
#define O_SPC  (O_SPZ + PV2)
#define O_SGT  (O_SPC + PV2)               // float4[NV] => 4*NV floats
#define O_SGST (O_SGT + 4 * NV)
#define O_RSES (O_SGST + GCELLS + 1)
#define O_PSES (O_RSES + NS + 1)
#define SM_FLOATS (O_PSES + NS + 1 + 8)

__global__ __launch_bounds__(TPB, 4) void k_mega(const float* __restrict__ obj,
                                                 const float* __restrict__ recon,
                                                 const float* __restrict__ gt,
                                                 const int* __restrict__ faces,
                                                 const float* __restrict__ mean,
                                                 const float* __restrict__ logv,
                                                 const float* __restrict__ rp,
                                                 const float* __restrict__ xp,
                                                 float* __restrict__ out) {
    __shared__ __align__(16) float S[SM_FLOATS];   // ~33.8KB
    __shared__ float s_red[20];
    __shared__ int   s_tile;
    const int tid = threadIdx.x;

    while (true) {
        __syncthreads();
        if (tid == 0) s_tile = atomicAdd(&g_ticket, 1);
        __syncthreads();
        const int tile = s_tile;
        if (tile >= NTILES) break;

        if (tile < T_CHAMT) {
            // ============ build tile (batch b): normals + all sorts ============
            const int b = tile;
            const float* rb = recon + (size_t)b * NV * 3;
            const float* gb = gt    + (size_t)b * NV * 3;

            // ---- normals ----
            {
                float* sx = S;          float* sy = S + NV;      float* sz = S + 2 * NV;
                float* nx = S + 3 * NV; float* ny = S + 4 * NV;  float* nz = S + 5 * NV;
                for (int v = tid; v < NV; v += TPB) {
                    sx[v] = rb[3*v+0]; sy[v] = rb[3*v+1]; sz[v] = rb[3*v+2];
                    nx[v] = 0.f; ny[v] = 0.f; nz[v] = 0.f;
                }
                __syncthreads();
                for (int f = tid; f < NFC; f += TPB) {
                    int i0 = faces[3*f+0], i1 = faces[3*f+1], i2 = faces[3*f+2];
                    float e1x = sx[i1]-sx[i0], e1y = sy[i1]-sy[i0], e1z = sz[i1]-sz[i0];
                    float e2x = sx[i2]-sx[i0], e2y = sy[i2]-sy[i0], e2z = sz[i2]-sz[i0];
                    float fx = e1y*e2z - e1z*e2y;
                    float fy = e1z*e2x - e1x*e2z;
                    float fz = e1x*e2y - e1y*e2x;
                    atomicAdd(&nx[i0], fx); atomicAdd(&ny[i0], fy); atomicAdd(&nz[i0], fz);
                    atomicAdd(&nx[i1], fx); atomicAdd(&ny[i1], fy); atomicAdd(&nz[i1], fz);
                    atomicAdd(&nx[i2], fx); atomicAdd(&ny[i2], fy); atomicAdd(&nz[i2], fz);
                }
                __syncthreads();
                float* vb = g_vn + (size_t)b * 3 * NV;
                for (int v = tid; v < NV; v += TPB) {
                    float x = nx[v], y = ny[v], z = nz[v];
                    float inv = 1.f / (sqrtf(x*x + y*y + z*z) + 1e-12f);
                    vb[v] = x*inv; vb[NV+v] = y*inv; vb[2*NV+v] = z*inv;
                }
                __syncthreads();
            }

            int* cnt = (int*)S;            // reuse scratch

            // ---- gt 4^3 grid sort ----
            for (int i = tid; i < GCELLS; i += TPB) cnt[i] = 0;
            __syncthreads();
            for (int v = tid; v < NV; v += TPB) {
                int c = (cell4(gb[3*v+2]) * GC + cell4(gb[3*v+1])) * GC + cell4(gb[3*v+0]);
                atomicAdd(&cnt[c], 1);
            }
            __syncthreads();
            if (tid == 0) {
                int run = 0;
                for (int c = 0; c < GCELLS; c++) { int t = cnt[c]; cnt[c] = run; g_gstart[b][c] = run; run += t; }
                g_gstart[b][GCELLS] = run;
            }
            __syncthreads();
            for (int v = tid; v < NV; v += TPB) {
                float x = gb[3*v+0], y = gb[3*v+1], z = gb[3*v+2];
                int c = (cell4(z) * GC + cell4(y)) * GC + cell4(x);
                int pos = atomicAdd(&cnt[c], 1);
                g_gsrt[b][pos] = make_float4(-2.f*x, -2.f*y, -2.f*z, fmaf(z, z, fmaf(y, y, x*x)));
            }
            __syncthreads();

            // ---- recon x-slab sort (padded) ----
            for (int i = tid; i < RV2; i += TPB) {
                g_rsrt[b][i] = make_float4(0.f, 0.f, 0.f, 3e37f);
                g_ridx[b][i] = 0;
            }
            for (int i = tid; i < NS; i += TPB) cnt[i] = 0;
            __syncthreads();
            for (int v = tid; v < NV; v += TPB) atomicAdd(&cnt[slab16(rb[3*v])], 1);
            __syncthreads();
            if (tid == 0) {
                int run = 0;
                for (int s = 0; s < NS; s++) {
                    g_rses[b][s] = run; int padded = (cnt[s] + 3) & ~3;
                    cnt[s] = run; run += padded;
                }
                g_rses[b][NS] = run;
            }
            __syncthreads();
            for (int v = tid; v < NV; v += TPB) {
                float x = rb[3*v+0], y = rb[3*v+1], z = rb[3*v+2];
                int pos = atomicAdd(&cnt[slab16(x)], 1);
                g_rsrt[b][pos] = make_float4(-2.f*x, -2.f*y, -2.f*z, fmaf(z, z, fmaf(y, y, x*x)));
                g_ridx[b][pos] = v;
            }
            __syncthreads();

            // ---- prior x-slab sort (padded) ----
            for (int i = tid; i < PV2; i += TPB) g_psrt[b][i] = make_float4(0.f, 0.f, 0.f, 3e37f);
            for (int i = tid; i < NS; i += TPB) cnt[i] = 0;
            __syncthreads();
            for (int i = tid; i < NP; i += TPB) atomicAdd(&cnt[slab16(rb[3*c_prior[i]])], 1);
            __syncthreads();
            if (tid == 0) {
                int run = 0;
                for (int s = 0; s < NS; s++) {
                    g_pses[b][s] = run; int padded = (cnt[s] + 3) & ~3;
                    cnt[s] = run; run += padded;
                }
                g_pses[b][NS] = run;
            }
            __syncthreads();
            for (int i = tid; i < NP; i += TPB) {
                int v = c_prior[i];
                float x = rb[3*v+0], y = rb[3*v+1], z = rb[3*v+2];
                int pos = atomicAdd(&cnt[slab16(x)], 1);
                g_psrt[b][pos] = make_float4(-2.f*x, -2.f*y, -2.f*z, fmaf(z, z, fmaf(y, y, x*x)));
            }
            __syncthreads();

            // ---- obj x-sort ----
            const float* ob = obj + (size_t)b * N1P * 3;
            for (int i = tid; i < NS; i += TPB) cnt[i] = 0;
            __syncthreads();
            for (int v = tid; v < N1P; v += TPB) atomicAdd(&cnt[slab16(ob[3*v])], 1);
            __syncthreads();
            if (tid == 0) {
                int run = 0;
                for (int s = 0; s < NS; s++) { int t = cnt[s]; cnt[s] = run; run += t; }
            }
            __syncthreads();
            for (int v = tid; v < N1P; v += TPB) {
                float x = ob[3*v+0], y = ob[3*v+1], z = ob[3*v+2];
                int pos = atomicAdd(&cnt[slab16(x)], 1);
                g_osrt[b][pos] = make_float4(x, y, z, fmaf(z, z, fmaf(y, y, x*x)));
            }
            __syncthreads();
            __threadfence();
            if (tid == 0) atomicExch(&g_bdone[b], 1);
        }
        else if (tile < T_MAINT) {
            // ============ chamfer tile (brute, no deps) ============
            const int c   = tile - T_CHAMT;
            const int b   = c >> 1;
            const int dir = c & 1;
            const float* srcp = (dir ? gt : recon) + (size_t)b * NV * 3;
            const float* tgtp = (dir ? recon : gt) + (size_t)b * NV * 3;
            float* tmx = S;        float* tmy = S + VP;
            float* tmz = S + 2*VP; float* tcc = S + 3*VP;
            for (int v = tid; v < VP; v += TPB) {
                if (v < NV) {
                    float x = tgtp[3*v+0], y = tgtp[3*v+1], z = tgtp[3*v+2];
                    tmx[v] = -2.f*x; tmy[v] = -2.f*y; tmz[v] = -2.f*z;
                    tcc[v] = fmaf(z, z, fmaf(y, y, x*x));
                } else { tmx[v]=0.f; tmy[v]=0.f; tmz[v]=0.f; tcc[v]=3e37f; }
            }
            __syncthreads();

            const int CROWS = 7;
            u64 CAX[CROWS], CAY[CROWS], CAZ[CROWS];
            float ca2[CROWS];
            bool  cok[CROWS];
            #pragma unroll
            for (int s = 0; s < CROWS; s++) {
                int r = tid + s * TPB;
                cok[s] = (r < NV);
                float x = 0.f, y = 0.f, z = 0.f;
                if (cok[s]) { x = srcp[3*r+0]; y = srcp[3*r+1]; z = srcp[3*r+2]; }
                ca2[s] = fmaf(z, z, fmaf(y, y, x*x));
                CAX[s] = bcast2(x); CAY[s] = bcast2(y); CAZ[s] = bcast2(z);
            }
            float cm0[CROWS];
            #pragma unroll
            for (int s = 0; s < CROWS; s++) cm0[s] = 3e38f;

            #pragma unroll 1
            for (int t = 0; t < VP; t += 4) {
                ulonglong2 X = *(const ulonglong2*)(tmx + t);
                ulonglong2 Y = *(const ulonglong2*)(tmy + t);
                ulonglong2 Z = *(const ulonglong2*)(tmz + t);
                ulonglong2 C = *(const ulonglong2*)(tcc + t);
                #pragma unroll
                for (int s = 0; s < CROWS; s++) {
                    u64 d2 = ffma2(CAZ[s], Z.x, ffma2(CAY[s], Y.x, ffma2(CAX[s], X.x, C.x)));
                    float lo1, hi1; unpack2f(d2, lo1, hi1);
                    d2 = ffma2(CAZ[s], Z.y, ffma2(CAY[s], Y.y, ffma2(CAX[s], X.y, C.y)));
                    float lo2, hi2; unpack2f(d2, lo2, hi2);
                    cm0[s] = fminf(cm0[s], fminf(fminf(lo1, hi1), fminf(lo2, hi2)));
                }
            }
            float part = 0.f;
            #pragma unroll
            for (int s = 0; s < CROWS; s++)
                if (cok[s]) part += fmaxf(cm0[s] + ca2[s], 0.f);

            for (int off = 16; off; off >>= 1) part += __shfl_down_sync(0xFFFFFFFFu, part, off);
            if ((tid & 31) == 0) s_red[tid >> 5] = part;
            __syncthreads();
            if (tid == 0)
                g_part_cham[c] = s_red[0] + s_red[1] + s_red[2] + s_red[3];
        }
        else {
            // ============ main tile: windowed sweeps ============
            const int m  = tile - T_MAINT;
            const int b  = m >> 4;
            const int xt = m & 15;

            if (tid == 0) { while (((volatile int*)g_bdone)[b] == 0) { } }
            __syncthreads();
            __threadfence();

            float* srx = S + O_SRX; float* sry = S + O_SRY;
            float* srz = S + O_SRZ; float* src = S + O_SRC;
            int*   sidx = (int*)(S + O_SIDX);
            float* spx = S + O_SPX; float* spy = S + O_SPY;
            float* spz = S + O_SPZ; float* spc = S + O_SPC;
            float4* sgt = (float4*)(S + O_SGT);
            int*   sgst = (int*)(S + O_SGST);
            int*   rses = (int*)(S + O_RSES);
            int*   pses = (int*)(S + O_PSES);

            for (int v = tid; v < RV2; v += TPB) {
                float4 T = __ldg(&g_rsrt[b][v]);
                srx[v] = T.x; sry[v] = T.y; srz[v] = T.z; src[v] = T.w;
                sidx[v] = __ldg(&g_ridx[b][v]);
            }
            for (int v = tid; v < PV2; v += TPB) {
                float4 T = __ldg(&g_psrt[b][v]);
                spx[v] = T.x; spy[v] = T.y; spz[v] = T.z; spc[v] = T.w;
            }
            for (int v = tid; v < NV; v += TPB) sgt[v] = __ldg(&g_gsrt[b][v]);
            for (int i = tid; i < GCELLS + 1; i += TPB) sgst[i] = g_gstart[b][i];
            for (int i = tid; i < NS + 1; i += TPB) { rses[i] = g_rses[b][i]; pses[i] = g_pses[b][i]; }
            __syncthreads();

            const int wid  = tid >> 5, lane = tid & 31;
            const unsigned FULL = 0xFFFFFFFFu;

            u64 AX[PTS], AY[PTS], AZ[PTS];
            float a2s[PTS];
            int   si[PTS];
            {
                const int base = xt * 512 + wid * 128 + lane;
                #pragma unroll
                for (int p = 0; p < PTS; p++) {
                    float4 P = __ldg(&g_osrt[b][base + p * 32]);
                    AX[p] = bcast2(P.x); AY[p] = bcast2(P.y); AZ[p] = bcast2(P.z);
                    a2s[p] = P.w;
                    si[p] = slab16(P.x);
                }
            }
            int smin = si[0], smax = si[0];
            #pragma unroll
            for (int p = 1; p < PTS; p++) { smin = min(smin, si[p]); smax = max(smax, si[p]); }
            smin = __reduce_min_sync(FULL, smin);
            smax = __reduce_max_sync(FULL, smax);

            float mr[PTS], mA[PTS];
            int   bt[PTS];
            #pragma unroll
            for (int p = 0; p < PTS; p++) { mr[p] = 3e38f; mA[p] = 3e38f; bt[p] = 0; }

            // ---- recon windowed sweep (min + argmin group) ----
            {
                auto scanSlab = [&](int s) {
                    const int t1 = rses[s + 1];
                    for (int t = rses[s]; t < t1; t += 4) {
                        ulonglong2 X = *(const ulonglong2*)(srx + t);
                        ulonglong2 Y = *(const ulonglong2*)(sry + t);
                        ulonglong2 Z = *(const ulonglong2*)(srz + t);
                        ulonglong2 C = *(const ulonglong2*)(src + t);
                        #pragma unroll
                        for (int p = 0; p < PTS; p++) {
                            u64 d2 = ffma2(AZ[p], Z.x, ffma2(AY[p], Y.x, ffma2(AX[p], X.x, C.x)));
                            float lo1, hi1; unpack2f(d2, lo1, hi1);
                            d2 = ffma2(AZ[p], Z.y, ffma2(AY[p], Y.y, ffma2(AX[p], X.y, C.y)));
                            float lo2, hi2; unpack2f(d2, lo2, hi2);
                            float h = fminf(fminf(lo1, hi1), fminf(lo2, hi2));
                            bool c = h < mr[p];
                            mr[p] = fminf(mr[p], h);
                            bt[p] = c ? t : bt[p];
                        }
                    }
                };
                int lo = smin, hi = smax;
                for (int s = lo; s <= hi; s++) scanSlab(s);
                while (true) {
                    bool safe = true;
                    #pragma unroll
                    for (int p = 0; p < PTS; p++) {
                        float dd = mr[p] + a2s[p];
                        float fl = (float)(si[p] - lo) * SW;
                        float fr = (float)(hi - si[p]) * SW;
                        bool ls = (lo == 0)      || (dd <= fl * fl);
                        bool rs = (hi == NS - 1) || (dd <= fr * fr);
                        safe = safe && ls && rs;
                    }
                    if (__all_sync(FULL, safe)) break;
                    bool ext = false;
                    if (lo > 0)      { lo--; scanSlab(lo); ext = true; }
                    if (hi < NS - 1) { hi++; scanSlab(hi); ext = true; }
                    if (!ext) break;
                }
            }

            // ---- prior windowed sweep (min only) ----
            {
                auto scanSlabP = [&](int s) {
                    const int t1 = pses[s + 1];
                    for (int t = pses[s]; t < t1; t += 4) {
                        ulonglong2 X = *(const ulonglong2*)(spx + t);
                        ulonglong2 Y = *(const ulonglong2*)(spy + t);
                        ulonglong2 Z = *(const ulonglong2*)(spz + t);
                        ulonglong2 C = *(const ulonglong2*)(spc + t);
                        #pragma unroll
                        for (int p = 0; p < PTS; p++) {
                            u64 d2 = ffma2(AZ[p], Z.x, ffma2(AY[p], Y.x, ffma2(AX[p], X.x, C.x)));
                            float lo1, hi1; unpack2f(d2, lo1, hi1);
                            d2 = ffma2(AZ[p], Z.y, ffma2(AY[p], Y.y, ffma2(AX[p], X.y, C.y)));
                            float lo2, hi2; unpack2f(d2, lo2, hi2);
                            mA[p] = fminf(mA[p], fminf(fminf(lo1, hi1), fminf(lo2, hi2)));
                        }
                    }
                };
                int lo = smin, hi = smax;
                for (int s = lo; s <= hi; s++) scanSlabP(s);
                while (true) {
                    bool safe = true;
                    #pragma unroll
                    for (int p = 0; p < PTS; p++) {
                        float dd = mA[p] + a2s[p];
                        float fl = (float)(si[p] - lo) * SW;
                        float fr = (float)(hi - si[p]) * SW;
                        bool ls = (lo == 0)      || (dd <= fl * fl);
                        bool rs = (hi == NS - 1) || (dd <= fr * fr);
                        safe = safe && ls && rs;
                    }
                    if (__all_sync(FULL, safe)) break;
                    bool ext = false;
                    if (lo > 0)      { lo--; scanSlabP(lo); ext = true; }
                    if (hi < NS - 1) { hi++; scanSlabP(hi); ext = true; }
                    if (!ext) break;
                }
            }

            // ---- epilogue ----
            float cm = 0.f, pen = 0.f, npn = 0.f, cons = 0.f, gtc = 0.f;
            const float* vb = g_vn + (size_t)b * 3 * NV;
            #pragma unroll
            for (int p = 0; p < PTS; p++) {
                float ax_, ay_, az_, junk;
                unpack2f(AX[p], ax_, junk);
                unpack2f(AY[p], ay_, junk);
                unpack2f(AZ[p], az_, junk);
                const float a2 = a2s[p];

                // gt boolean via 4^3 cube scan
                bool gc = false;
                {
                    int x0 = cell4(ax_ - GRAD), x1 = cell4(ax_ + GRAD);
                    int y0 = cell4(ay_ - GRAD), y1 = cell4(ay_ + GRAD);
                    int z0 = cell4(az_ - GRAD), z1 = cell4(az_ + GRAD);
                    for (int zz = z0; zz <= z1; zz++)
                    for (int yy = y0; yy <= y1; yy++)
                    for (int xx = x0; xx <= x1; xx++) {
                        int c = (zz * GC + yy) * GC + xx;
                        int s0 = sgst[c], s1 = sgst[c + 1];
                        for (int j = s0; j < s1; j++) {
                            float4 T = sgt[j];
                            float d = fmaf(az_, T.z, fmaf(ay_, T.y, fmaf(ax_, T.x, T.w)));
                            gc |= (d + a2 < GTHR);
                        }
                    }
                }

                // exact argmin recovery within winning group
                const int t = bt[p];
                const float m2 = mr[p];
                int slot = t;
                #pragma unroll
                for (int jj = 3; jj >= 0; jj--) {
                    int j = t + jj;
                    float dj = fmaf(az_, srz[j], fmaf(ay_, sry[j], fmaf(ax_, srx[j], src[j])));
                    if (dj == m2) slot = j;
                }
                const int idx = sidx[slot];
                float drec = fmaxf(m2 + a2, 0.f);
                float dpr  = fmaxf(mA[p] + a2, 0.f);
                if (drec < 1e-4f) { cm += dpr; npn += 1.f; }
                bool rc = sqrtf(drec) < 0.005f;
                if (gc) { gtc += 1.f; if (rc) cons += 1.f; }
                float nvx = -0.5f * srx[slot], nvy = -0.5f * sry[slot], nvz = -0.5f * srz[slot];
                float dot = (nvx - ax_) * __ldcg(vb + idx)
                          + (nvy - ay_) * __ldcg(vb + NV + idx)
                          + (nvz - az_) * __ldcg(vb + 2 * NV + idx);
                if (dot > 0.f) pen += drec;
            }

            for (int off = 16; off; off >>= 1) {
                cm   += __shfl_down_sync(FULL, cm,   off);
                pen  += __shfl_down_sync(FULL, pen,  off);
                npn  += __shfl_down_sync(FULL, npn,  off);
                cons += __shfl_down_sync(FULL, cons, off);
                gtc  += __shfl_down_sync(FULL, gtc,  off);
            }
            if (lane == 0) {
                s_red[wid]      = cm;   s_red[4 + wid]  = pen;
                s_red[8 + wid]  = npn;  s_red[12 + wid] = cons;
                s_red[16 + wid] = gtc;
            }
            __syncthreads();
            if (tid == 0) {
                float c = 0, p = 0, n = 0, co = 0, g = 0;
                for (int w = 0; w < 4; w++) {
                    c += s_red[w]; p += s_red[4+w]; n += s_red[8+w];
                    co += s_red[12+w]; g += s_red[16+w];
                }
                float* gp = g_part_main + (size_t)m * 5;
                gp[0] = c; gp[1] = p; gp[2] = n; gp[3] = co; gp[4] = g;
            }
        }
    }

    // ================= finale: last block combines =================
    __syncthreads();
    if (tid == 0) {
        __threadfence();
        int r = atomicAdd(&g_fin, 1);
        s_tile = (r == NBLOCKS - 1) ? 1 : 0;
    }
    __syncthreads();
    if (s_tile) {
        __threadfence();
        float sp = 0.f, sk = 0.f, sc = 0.f;
        float scm = 0.f, spe = 0.f, snp = 0.f, sco = 0.f, sgt2 = 0.f;
        for (int i = tid; i < BN * 61; i += TPB) { float d = rp[i] - xp[i]; sp += d * d; }
        for (int i = tid; i < BN * 64; i += TPB) {
            float m = mean[i], lv = logv[i];
            sk += 1.f + lv - m*m - expf(lv);
        }
        for (int i = tid; i < NTILE_CHAM; i += TPB) sc += g_part_cham[i];
        for (int i = tid; i < NTILE_MAIN; i += TPB) {
            const float* gp = g_part_main + (size_t)i * 5;
            scm += gp[0]; spe += gp[1]; snp += gp[2]; sco += gp[3]; sgt2 += gp[4];
        }
        for (int off = 16; off; off >>= 1) {
            sp   += __shfl_down_sync(0xFFFFFFFFu, sp,   off);
            sk   += __shfl_down_sync(0xFFFFFFFFu, sk,   off);
            sc   += __shfl_down_sync(0xFFFFFFFFu, sc,   off);
            scm  += __shfl_down_sync(0xFFFFFFFFu, scm,  off);
            spe  += __shfl_down_sync(0xFFFFFFFFu, spe,  off);
            snp  += __shfl_down_sync(0xFFFFFFFFu, snp,  off);
            sco  += __shfl_down_sync(0xFFFFFFFFu, sco,  off);
            sgt2 += __shfl_down_sync(0xFFFFFFFFu, sgt2, off);
        }
        const int wid = tid >> 5;
        if ((tid & 31) == 0) {
            s_red[wid]      = sp;  s_red[4 + wid]  = sk;
            s_red[8 + wid]  = sc;  s_red[12 + wid] = scm;
            S[wid] = spe; S[4 + wid] = snp; S[8 + wid] = sco; S[12 + wid] = sgt2;
        }
        __syncthreads();
        if (tid == 0) {
            float t0=0,t1=0,t2=0,t3=0,t4=0,t5=0,t6=0,t7=0;
            for (int w = 0; w < 4; w++) {
                t0 += s_red[w]; t1 += s_red[4+w]; t2 += s_red[8+w]; t3 += s_red[12+w];
                t4 += S[w];     t5 += S[4+w];     t6 += S[8+w];     t7 += S[12+w];
            }
            double param_loss  = (double)t0 / 64.0;
            double KLD         = -0.5 * (double)t1 / 64.0 * 10.0;
            double recon_loss  = (double)t2 / 64.0;
            double cmap_loss   = 3000.0 * (double)t3 / (64.0 * (double)t5);
            double consistency = -5.0 * (double)t6 / ((double)t7 + 0.0001);
            double penetr      = 100.0 * (double)t4 / 64.0;
            double loss = (recon_loss + KLD) + 0.1 * param_loss
                        + 1000.0 * cmap_loss + 10.0 * consistency + 10.0 * penetr;
            out[0] = (float)loss;
        }
        for (int i = tid; i < BN; i += TPB) g_bdone[i] = 0;
        __syncthreads();
        if (tid == 0) { g_ticket = 0; g_fin = 0; __threadfence(); }
    }
}

extern "C" void kernel_launch(void* const* d_in, const int* in_sizes, int n_in,
                              void* d_out, int out_size) {
    const float* obj   = (const float*)d_in[0];
    const float* recon = (const float*)d_in[1];
    const float* gt    = (const float*)d_in[2];
    const float* mean  = (const float*)d_in[3];
    const float* logv  = (const float*)d_in[4];
    const float* rp    = (const float*)d_in[5];
    const float* xp    = (const float*)d_in[6];
    const int*   faces = (const int*)d_in[7];
    float* out = (float*)d_out;

    k_mega<<<NBLOCKS, TPB>>>(obj, recon, gt, faces, mean, logv, rp, xp, out);
}

// round 17
// speedup vs baseline: 13.0731x; 1.2006x over previous
#include <cuda_runtime.h>
#include <math.h>

#define BN   64
#define N1P  8192
#define NV   778
#define VP   780
#define NFC  1538
#define NP   204

#define PTS   4
#define TPB   128
#define MAIN_GX    16
#define NTILE_MAIN (MAIN_GX * BN)          // 1024
#define NTILE_CHAM (2 * BN)                // 128
// tickets: [0,64) build, [64,192) chamfer (no deps), [192,1216) main
#define T_CHAMT    64
#define T_MAINT    192
#define NTILES     (T_MAINT + NTILE_MAIN)  // 1216
#define NBLOCKS    (148 * 4)               // 592

// x-slabs
#define NS     16
#define SW     0.00625f
#define SWINV  160.0f
#define RV2    832                         // padded slab capacity (recon/gt)
#define PV2    256                         // padded prior capacity

#define GTHR   2.5e-5f                     // 0.005^2

__device__ float  g_vn[BN * 3 * NV];
__device__ float4 g_osrt[BN][N1P];         // obj sorted by x: (x,y,z,a2)
__device__ float4 g_rsrt[BN][RV2];         // recon slab-sorted: (-2x,-2y,-2z,c)
__device__ int    g_ridx[BN][RV2];
__device__ int    g_rses[BN][NS + 1];
__device__ float4 g_psrt[BN][PV2];
__device__ int    g_pses[BN][NS + 1];
__device__ float4 g_gsrt[BN][RV2];         // gt slab-sorted: (-2x,-2y,-2z,c)
__device__ int    g_gses[BN][NS + 1];
__device__ float  g_part_main[NTILE_MAIN * 5];
__device__ float  g_part_cham[NTILE_CHAM];
__device__ int    g_ticket = 0;
__device__ int    g_bdone[BN];
__device__ int    g_fin = 0;

__constant__ int c_prior[NP] = {
697,698,699,700,712,713,714,715,737,738,739,740,741,743,744,745,746,748,749,750,
753,754,755,756,757,758,759,760,761,762,763,764,765,766,767,768,
46,47,48,49,164,165,166,167,194,195,223,237,238,280,281,298,301,317,320,323,
324,325,326,327,328,329,330,331,332,333,340,341,342,343,344,345,346,347,348,349,
350,351,352,353,354,355,
356,357,358,359,375,376,386,387,396,397,402,403,413,429,433,434,435,436,437,438,
439,440,441,442,443,444,452,453,454,455,456,459,460,461,462,463,464,465,466,467,
468,469,470,471,484,485,486,496,497,506,507,513,514,524,545,546,547,548,549,550,
551,552,553,555,563,564,565,566,567,570,572,573,574,575,576,577,578,
580,581,582,583,600,601,602,614,615,624,625,630,631,641,663,664,665,666,667,668,
670,672,680,681,682,683,684,686,687,688,689,690,691,692,693,694,695,
73,96,98,99,772,774,775,777};

typedef unsigned long long u64;

__device__ __forceinline__ u64 ffma2(u64 a, u64 b, u64 c) {
    u64 d;
    asm("fma.rn.f32x2 %0, %1, %2, %3;" : "=l"(d) : "l"(a), "l"(b), "l"(c));
    return d;
}
__device__ __forceinline__ u64 bcast2(float x) {
    u64 r;
    asm("mov.b64 %0, {%1, %2};" : "=l"(r) : "f"(x), "f"(x));
    return r;
}
__device__ __forceinline__ void unpack2f(u64 v, float& lo, float& hi) {
    asm("mov.b64 {%0, %1}, %2;" : "=f"(lo), "=f"(hi) : "l"(v));
}
__device__ __forceinline__ int slab16(float x) {
    int c = (int)(x * SWINV);
    return c < 0 ? 0 : (c > NS - 1 ? NS - 1 : c);
}

// smem layout (floats)
#define O_SRX  0
#define O_SRY  (O_SRX + RV2)
#define O_SRZ  (O_SRY + RV2)
#define O_SRC  (O_SRZ + RV2)
#define O_SIDX (O_SRC + RV2)
#define O_SPX  (O_SIDX + RV2)
#define O_SPY  (O_SPX + PV2)
#define O_SPZ  (O_SPY + PV2)
#define O_SPC  (O_SPZ + PV2)
#define O_SGX  (O_SPC + PV2)
#define O_SGY  (O_SGX + RV2)
#define O_SGZ  (O_SGY + RV2)
#define O_SGC  (O_SGZ + RV2)
#define O_RSES (O_SGC + RV2)
#define O_PSES (O_RSES + NS + 1)
#define O_GSES (O_PSES + NS + 1)
#define SM_FLOATS (O_GSES + NS + 1 + 8)    // ~8620 floats ≈ 34.5KB

__global__ __launch_bounds__(TPB, 4) void k_mega(const float* __restrict__ obj,
                                                 const float* __restrict__ recon,
                                                 const float* __restrict__ gt,
                                                 const int* __restrict__ faces,
                                                 const float* __restrict__ mean,
                                                 const float* __restrict__ logv,
                                                 const float* __restrict__ rp,
                                                 const float* __restrict__ xp,
                                                 float* __restrict__ out) {
    __shared__ __align__(16) float S[SM_FLOATS];
    __shared__ float s_red[20];
    __shared__ int   s_tile;
    const int tid = threadIdx.x;

    while (true) {
        __syncthreads();
        if (tid == 0) s_tile = atomicAdd(&g_ticket, 1);
        __syncthreads();
        const int tile = s_tile;
        if (tile >= NTILES) break;

        if (tile < T_CHAMT) {
            // ============ build tile (batch b): normals + slab sorts ============
            const int b = tile;
            const float* rb = recon + (size_t)b * NV * 3;
            const float* gb = gt    + (size_t)b * NV * 3;

            // ---- normals ----
            {
                float* sx = S;          float* sy = S + NV;      float* sz = S + 2 * NV;
                float* nx = S + 3 * NV; float* ny = S + 4 * NV;  float* nz = S + 5 * NV;
                for (int v = tid; v < NV; v += TPB) {
                    sx[v] = rb[3*v+0]; sy[v] = rb[3*v+1]; sz[v] = rb[3*v+2];
                    nx[v] = 0.f; ny[v] = 0.f; nz[v] = 0.f;
                }
                __syncthreads();
                for (int f = tid; f < NFC; f += TPB) {
                    int i0 = faces[3*f+0], i1 = faces[3*f+1], i2 = faces[3*f+2];
                    float e1x = sx[i1]-sx[i0], e1y = sy[i1]-sy[i0], e1z = sz[i1]-sz[i0];
                    float e2x = sx[i2]-sx[i0], e2y = sy[i2]-sy[i0], e2z = sz[i2]-sz[i0];
                    float fx = e1y*e2z - e1z*e2y;
                    float fy = e1z*e2x - e1x*e2z;
                    float fz = e1x*e2y - e1y*e2x;
                    atomicAdd(&nx[i0], fx); atomicAdd(&ny[i0], fy); atomicAdd(&nz[i0], fz);
                    atomicAdd(&nx[i1], fx); atomicAdd(&ny[i1], fy); atomicAdd(&nz[i1], fz);
                    atomicAdd(&nx[i2], fx); atomicAdd(&ny[i2], fy); atomicAdd(&nz[i2], fz);
                }
                __syncthreads();
                float* vb = g_vn + (size_t)b * 3 * NV;
                for (int v = tid; v < NV; v += TPB) {
                    float x = nx[v], y = ny[v], z = nz[v];
                    float inv = 1.f / (sqrtf(x*x + y*y + z*z) + 1e-12f);
                    vb[v] = x*inv; vb[NV+v] = y*inv; vb[2*NV+v] = z*inv;
                }
                __syncthreads();
            }

            int* cnt = (int*)S;

            // ---- recon x-slab sort (padded) ----
            for (int i = tid; i < RV2; i += TPB) {
                g_rsrt[b][i] = make_float4(0.f, 0.f, 0.f, 3e37f);
                g_ridx[b][i] = 0;
            }
            for (int i = tid; i < NS; i += TPB) cnt[i] = 0;
            __syncthreads();
            for (int v = tid; v < NV; v += TPB) atomicAdd(&cnt[slab16(rb[3*v])], 1);
            __syncthreads();
            if (tid == 0) {
                int run = 0;
                for (int s = 0; s < NS; s++) {
                    g_rses[b][s] = run; int padded = (cnt[s] + 3) & ~3;
                    cnt[s] = run; run += padded;
                }
                g_rses[b][NS] = run;
            }
            __syncthreads();
            for (int v = tid; v < NV; v += TPB) {
                float x = rb[3*v+0], y = rb[3*v+1], z = rb[3*v+2];
                int pos = atomicAdd(&cnt[slab16(x)], 1);
                g_rsrt[b][pos] = make_float4(-2.f*x, -2.f*y, -2.f*z, fmaf(z, z, fmaf(y, y, x*x)));
                g_ridx[b][pos] = v;
            }
            __syncthreads();

            // ---- gt x-slab sort (padded) ----
            for (int i = tid; i < RV2; i += TPB)
                g_gsrt[b][i] = make_float4(0.f, 0.f, 0.f, 3e37f);
            for (int i = tid; i < NS; i += TPB) cnt[i] = 0;
            __syncthreads();
            for (int v = tid; v < NV; v += TPB) atomicAdd(&cnt[slab16(gb[3*v])], 1);
            __syncthreads();
            if (tid == 0) {
                int run = 0;
                for (int s = 0; s < NS; s++) {
                    g_gses[b][s] = run; int padded = (cnt[s] + 3) & ~3;
                    cnt[s] = run; run += padded;
                }
                g_gses[b][NS] = run;
            }
            __syncthreads();
            for (int v = tid; v < NV; v += TPB) {
                float x = gb[3*v+0], y = gb[3*v+1], z = gb[3*v+2];
                int pos = atomicAdd(&cnt[slab16(x)], 1);
                g_gsrt[b][pos] = make_float4(-2.f*x, -2.f*y, -2.f*z, fmaf(z, z, fmaf(y, y, x*x)));
            }
            __syncthreads();

            // ---- prior x-slab sort (padded) ----
            for (int i = tid; i < PV2; i += TPB) g_psrt[b][i] = make_float4(0.f, 0.f, 0.f, 3e37f);
            for (int i = tid; i < NS; i += TPB) cnt[i] = 0;
            __syncthreads();
            for (int i = tid; i < NP; i += TPB) atomicAdd(&cnt[slab16(rb[3*c_prior[i]])], 1);
            __syncthreads();
            if (tid == 0) {
                int run = 0;
                for (int s = 0; s < NS; s++) {
                    g_pses[b][s] = run; int padded = (cnt[s] + 3) & ~3;
                    cnt[s] = run; run += padded;
                }
                g_pses[b][NS] = run;
            }
            __syncthreads();
            for (int i = tid; i < NP; i += TPB) {
                int v = c_prior[i];
                float x = rb[3*v+0], y = rb[3*v+1], z = rb[3*v+2];
                int pos = atomicAdd(&cnt[slab16(x)], 1);
                g_psrt[b][pos] = make_float4(-2.f*x, -2.f*y, -2.f*z, fmaf(z, z, fmaf(y, y, x*x)));
            }
            __syncthreads();

            // ---- obj x-sort ----
            const float* ob = obj + (size_t)b * N1P * 3;
            for (int i = tid; i < NS; i += TPB) cnt[i] = 0;
            __syncthreads();
            for (int v = tid; v < N1P; v += TPB) atomicAdd(&cnt[slab16(ob[3*v])], 1);
            __syncthreads();
            if (tid == 0) {
                int run = 0;
                for (int s = 0; s < NS; s++) { int t = cnt[s]; cnt[s] = run; run += t; }
            }
            __syncthreads();
            for (int v = tid; v < N1P; v += TPB) {
                float x = ob[3*v+0], y = ob[3*v+1], z = ob[3*v+2];
                int pos = atomicAdd(&cnt[slab16(x)], 1);
                g_osrt[b][pos] = make_float4(x, y, z, fmaf(z, z, fmaf(y, y, x*x)));
            }
            __syncthreads();
            __threadfence();
            if (tid == 0) atomicExch(&g_bdone[b], 1);
        }
        else if (tile < T_MAINT) {
            // ============ chamfer tile (brute, no deps) ============
            const int c   = tile - T_CHAMT;
            const int b   = c >> 1;
            const int dir = c & 1;
            const float* srcp = (dir ? gt : recon) + (size_t)b * NV * 3;
            const float* tgtp = (dir ? recon : gt) + (size_t)b * NV * 3;
            float* tmx = S;        float* tmy = S + VP;
            float* tmz = S + 2*VP; float* tcc = S + 3*VP;
            for (int v = tid; v < VP; v += TPB) {
                if (v < NV) {
                    float x = tgtp[3*v+0], y = tgtp[3*v+1], z = tgtp[3*v+2];
                    tmx[v] = -2.f*x; tmy[v] = -2.f*y; tmz[v] = -2.f*z;
                    tcc[v] = fmaf(z, z, fmaf(y, y, x*x));
                } else { tmx[v]=0.f; tmy[v]=0.f; tmz[v]=0.f; tcc[v]=3e37f; }
            }
            __syncthreads();

            const int CROWS = 7;
            u64 CAX[CROWS], CAY[CROWS], CAZ[CROWS];
            float ca2[CROWS];
            bool  cok[CROWS];
            #pragma unroll
            for (int s = 0; s < CROWS; s++) {
                int r = tid + s * TPB;
                cok[s] = (r < NV);
                float x = 0.f, y = 0.f, z = 0.f;
                if (cok[s]) { x = srcp[3*r+0]; y = srcp[3*r+1]; z = srcp[3*r+2]; }
                ca2[s] = fmaf(z, z, fmaf(y, y, x*x));
                CAX[s] = bcast2(x); CAY[s] = bcast2(y); CAZ[s] = bcast2(z);
            }
            float cm0[CROWS];
            #pragma unroll
            for (int s = 0; s < CROWS; s++) cm0[s] = 3e38f;

            #pragma unroll 1
            for (int t = 0; t < VP; t += 4) {
                ulonglong2 X = *(const ulonglong2*)(tmx + t);
                ulonglong2 Y = *(const ulonglong2*)(tmy + t);
                ulonglong2 Z = *(const ulonglong2*)(tmz + t);
                ulonglong2 C = *(const ulonglong2*)(tcc + t);
                #pragma unroll
                for (int s = 0; s < CROWS; s++) {
                    u64 d2 = ffma2(CAZ[s], Z.x, ffma2(CAY[s], Y.x, ffma2(CAX[s], X.x, C.x)));
                    float lo1, hi1; unpack2f(d2, lo1, hi1);
                    d2 = ffma2(CAZ[s], Z.y, ffma2(CAY[s], Y.y, ffma2(CAX[s], X.y, C.y)));
                    float lo2, hi2; unpack2f(d2, lo2, hi2);
                    cm0[s] = fminf(cm0[s], fminf(fminf(lo1, hi1), fminf(lo2, hi2)));
                }
            }
            float part = 0.f;
            #pragma unroll
            for (int s = 0; s < CROWS; s++)
                if (cok[s]) part += fmaxf(cm0[s] + ca2[s], 0.f);

            for (int off = 16; off; off >>= 1) part += __shfl_down_sync(0xFFFFFFFFu, part, off);
            if ((tid & 31) == 0) s_red[tid >> 5] = part;
            __syncthreads();
            if (tid == 0)
                g_part_cham[c] = s_red[0] + s_red[1] + s_red[2] + s_red[3];
        }
        else {
            // ============ main tile: three windowed slab sweeps ============
            const int m  = tile - T_MAINT;
            const int b  = m >> 4;
            const int xt = m & 15;

            if (tid == 0) { while (((volatile int*)g_bdone)[b] == 0) { } }
            __syncthreads();
            __threadfence();

            float* srx = S + O_SRX; float* sry = S + O_SRY;
            float* srz = S + O_SRZ; float* src = S + O_SRC;
            int*   sidx = (int*)(S + O_SIDX);
            float* spx = S + O_SPX; float* spy = S + O_SPY;
            float* spz = S + O_SPZ; float* spc = S + O_SPC;
            float* sgx = S + O_SGX; float* sgy = S + O_SGY;
            float* sgz = S + O_SGZ; float* sgc = S + O_SGC;
            int*   rses = (int*)(S + O_RSES);
            int*   pses = (int*)(S + O_PSES);
            int*   gses = (int*)(S + O_GSES);

            for (int v = tid; v < RV2; v += TPB) {
                float4 T = __ldg(&g_rsrt[b][v]);
                srx[v] = T.x; sry[v] = T.y; srz[v] = T.z; src[v] = T.w;
                sidx[v] = __ldg(&g_ridx[b][v]);
                float4 G = __ldg(&g_gsrt[b][v]);
                sgx[v] = G.x; sgy[v] = G.y; sgz[v] = G.z; sgc[v] = G.w;
            }
            for (int v = tid; v < PV2; v += TPB) {
                float4 T = __ldg(&g_psrt[b][v]);
                spx[v] = T.x; spy[v] = T.y; spz[v] = T.z; spc[v] = T.w;
            }
            for (int i = tid; i < NS + 1; i += TPB) {
                rses[i] = g_rses[b][i]; pses[i] = g_pses[b][i]; gses[i] = g_gses[b][i];
            }
            __syncthreads();

            const int wid  = tid >> 5, lane = tid & 31;
            const unsigned FULL = 0xFFFFFFFFu;

            u64 AX[PTS], AY[PTS], AZ[PTS];
            float a2s[PTS];
            int   si[PTS];
            {
                const int base = xt * 512 + wid * 128 + lane;
                #pragma unroll
                for (int p = 0; p < PTS; p++) {
                    float4 P = __ldg(&g_osrt[b][base + p * 32]);
                    AX[p] = bcast2(P.x); AY[p] = bcast2(P.y); AZ[p] = bcast2(P.z);
                    a2s[p] = P.w;
                    si[p] = slab16(P.x);
                }
            }
            int smin = si[0], smax = si[0];
            #pragma unroll
            for (int p = 1; p < PTS; p++) { smin = min(smin, si[p]); smax = max(smax, si[p]); }
            smin = __reduce_min_sync(FULL, smin);
            smax = __reduce_max_sync(FULL, smax);

            float mr[PTS], mA[PTS], mG[PTS];
            int   bt[PTS];
            #pragma unroll
            for (int p = 0; p < PTS; p++) { mr[p] = 3e38f; mA[p] = 3e38f; mG[p] = 3e38f; bt[p] = 0; }

            // ---- recon windowed sweep (min + argmin group) ----
            {
                auto scanSlab = [&](int s) {
                    const int t1 = rses[s + 1];
                    for (int t = rses[s]; t < t1; t += 4) {
                        ulonglong2 X = *(const ulonglong2*)(srx + t);
                        ulonglong2 Y = *(const ulonglong2*)(sry + t);
                        ulonglong2 Z = *(const ulonglong2*)(srz + t);
                        ulonglong2 C = *(const ulonglong2*)(src + t);
                        #pragma unroll
                        for (int p = 0; p < PTS; p++) {
                            u64 d2 = ffma2(AZ[p], Z.x, ffma2(AY[p], Y.x, ffma2(AX[p], X.x, C.x)));
                            float lo1, hi1; unpack2f(d2, lo1, hi1);
                            d2 = ffma2(AZ[p], Z.y, ffma2(AY[p], Y.y, ffma2(AX[p], X.y, C.y)));
                            float lo2, hi2; unpack2f(d2, lo2, hi2);
                            float h = fminf(fminf(lo1, hi1), fminf(lo2, hi2));
                            bool c = h < mr[p];
                            mr[p] = fminf(mr[p], h);
                            bt[p] = c ? t : bt[p];
                        }
                    }
                };
                int lo = smin, hi = smax;
                for (int s = lo; s <= hi; s++) scanSlab(s);
                while (true) {
                    bool safe = true;
                    #pragma unroll
                    for (int p = 0; p < PTS; p++) {
                        float dd = mr[p] + a2s[p];
                        float fl = (float)(si[p] - lo) * SW;
                        float fr = (float)(hi - si[p]) * SW;
                        bool ls = (lo == 0)      || (dd <= fl * fl);
                        bool rs = (hi == NS - 1) || (dd <= fr * fr);
                        safe = safe && ls && rs;
                    }
                    if (__all_sync(FULL, safe)) break;
                    bool ext = false;
                    if (lo > 0)      { lo--; scanSlab(lo); ext = true; }
                    if (hi < NS - 1) { hi++; scanSlab(hi); ext = true; }
                    if (!ext) break;
                }
            }

            // ---- gt fixed-window sweep (boolean: ±1 slab suffices for 0.005) ----
            {
                const int glo = max(0, smin - 1), ghi = min(NS - 1, smax + 1);
                for (int s = glo; s <= ghi; s++) {
                    const int t1 = gses[s + 1];
                    for (int t = gses[s]; t < t1; t += 4) {
                        ulonglong2 X = *(const ulonglong2*)(sgx + t);
                        ulonglong2 Y = *(const ulonglong2*)(sgy + t);
                        ulonglong2 Z = *(const ulonglong2*)(sgz + t);
                        ulonglong2 C = *(const ulonglong2*)(sgc + t);
                        #pragma unroll
                        for (int p = 0; p < PTS; p++) {
                            u64 d2 = ffma2(AZ[p], Z.x, ffma2(AY[p], Y.x, ffma2(AX[p], X.x, C.x)));
                            float lo1, hi1; unpack2f(d2, lo1, hi1);
                            d2 = ffma2(AZ[p], Z.y, ffma2(AY[p], Y.y, ffma2(AX[p], X.y, C.y)));
                            float lo2, hi2; unpack2f(d2, lo2, hi2);
                            mG[p] = fminf(mG[p], fminf(fminf(lo1, hi1), fminf(lo2, hi2)));
                        }
                    }
                }
            }

            // ---- prior windowed sweep (min only) ----
            {
                auto scanSlabP = [&](int s) {
                    const int t1 = pses[s + 1];
                    for (int t = pses[s]; t < t1; t += 4) {
                        ulonglong2 X = *(const ulonglong2*)(spx + t);
                        ulonglong2 Y = *(const ulonglong2*)(spy + t);
                        ulonglong2 Z = *(const ulonglong2*)(spz + t);
                        ulonglong2 C = *(const ulonglong2*)(spc + t);
                        #pragma unroll
                        for (int p = 0; p < PTS; p++) {
                            u64 d2 = ffma2(AZ[p], Z.x, ffma2(AY[p], Y.x, ffma2(AX[p], X.x, C.x)));
                            float lo1, hi1; unpack2f(d2, lo1, hi1);
                            d2 = ffma2(AZ[p], Z.y, ffma2(AY[p], Y.y, ffma2(AX[p], X.y, C.y)));
                            float lo2, hi2; unpack2f(d2, lo2, hi2);
                            mA[p] = fminf(mA[p], fminf(fminf(lo1, hi1), fminf(lo2, hi2)));
                        }
                    }
                };
                int lo = smin, hi = smax;
                for (int s = lo; s <= hi; s++) scanSlabP(s);
                while (true) {
                    bool safe = true;
                    #pragma unroll
                    for (int p = 0; p < PTS; p++) {
                        float dd = mA[p] + a2s[p];
                        float fl = (float)(si[p] - lo) * SW;
                        float fr = (float)(hi - si[p]) * SW;
                        bool ls = (lo == 0)      || (dd <= fl * fl);
                        bool rs = (hi == NS - 1) || (dd <= fr * fr);
                        safe = safe && ls && rs;
                    }
                    if (__all_sync(FULL, safe)) break;
                    bool ext = false;
                    if (lo > 0)      { lo--; scanSlabP(lo); ext = true; }
                    if (hi < NS - 1) { hi++; scanSlabP(hi); ext = true; }
                    if (!ext) break;
                }
            }

            // ---- epilogue (no gt scan — pure arithmetic) ----
            float cm = 0.f, pen = 0.f, npn = 0.f, cons = 0.f, gtc = 0.f;
            const float* vb = g_vn + (size_t)b * 3 * NV;
            #pragma unroll
            for (int p = 0; p < PTS; p++) {
                float ax_, ay_, az_, junk;
                unpack2f(AX[p], ax_, junk);
                unpack2f(AY[p], ay_, junk);
                unpack2f(AZ[p], az_, junk);
                const float a2 = a2s[p];

                const int t = bt[p];
                const float m2 = mr[p];
                int slot = t;
                #pragma unroll
                for (int jj = 3; jj >= 0; jj--) {
                    int j = t + jj;
                    float dj = fmaf(az_, srz[j], fmaf(ay_, sry[j], fmaf(ax_, srx[j], src[j])));
                    if (dj == m2) slot = j;
                }
                const int idx = sidx[slot];
                float drec = fmaxf(m2 + a2, 0.f);
                float dpr  = fmaxf(mA[p] + a2, 0.f);
                bool  gc   = (mG[p] + a2 < GTHR);
                if (drec < 1e-4f) { cm += dpr; npn += 1.f; }
                bool rc = sqrtf(drec) < 0.005f;
                if (gc) { gtc += 1.f; if (rc) cons += 1.f; }
                float nvx = -0.5f * srx[slot], nvy = -0.5f * sry[slot], nvz = -0.5f * srz[slot];
                float dot = (nvx - ax_) * __ldcg(vb + idx)
                          + (nvy - ay_) * __ldcg(vb + NV + idx)
                          + (nvz - az_) * __ldcg(vb + 2 * NV + idx);
                if (dot > 0.f) pen += drec;
            }

            for (int off = 16; off; off >>= 1) {
                cm   += __shfl_down_sync(FULL, cm,   off);
                pen  += __shfl_down_sync(FULL, pen,  off);
                npn  += __shfl_down_sync(FULL, npn,  off);
                cons += __shfl_down_sync(FULL, cons, off);
                gtc  += __shfl_down_sync(FULL, gtc,  off);
            }
            if (lane == 0) {
                s_red[wid]      = cm;   s_red[4 + wid]  = pen;
                s_red[8 + wid]  = npn;  s_red[12 + wid] = cons;
                s_red[16 + wid] = gtc;
            }
            __syncthreads();
            if (tid == 0) {
                float c = 0, p = 0, n = 0, co = 0, g = 0;
                for (int w = 0; w < 4; w++) {
                    c += s_red[w]; p += s_red[4+w]; n += s_red[8+w];
                    co += s_red[12+w]; g += s_red[16+w];
                }
                float* gp = g_part_main + (size_t)m * 5;
                gp[0] = c; gp[1] = p; gp[2] = n; gp[3] = co; gp[4] = g;
            }
        }
    }

    // ================= finale: last block combines =================
    __syncthreads();
    if (tid == 0) {
        __threadfence();
        int r = atomicAdd(&g_fin, 1);
        s_tile = (r == NBLOCKS - 1) ? 1 : 0;
    }
    __syncthreads();
    if (s_tile) {
        __threadfence();
        float sp = 0.f, sk = 0.f, sc = 0.f;
        float scm = 0.f, spe = 0.f, snp = 0.f, sco = 0.f, sgt2 = 0.f;
        for (int i = tid; i < BN * 61; i += TPB) { float d = rp[i] - xp[i]; sp += d * d; }
        for (int i = tid; i < BN * 64; i += TPB) {
            float m = mean[i], lv = logv[i];
            sk += 1.f + lv - m*m - expf(lv);
        }
        for (int i = tid; i < NTILE_CHAM; i += TPB) sc += g_part_cham[i];
        for (int i = tid; i < NTILE_MAIN; i += TPB) {
            const float* gp = g_part_main + (size_t)i * 5;
            scm += gp[0]; spe += gp[1]; snp += gp[2]; sco += gp[3]; sgt2 += gp[4];
        }
        for (int off = 16; off; off >>= 1) {
            sp   += __shfl_down_sync(0xFFFFFFFFu, sp,   off);
            sk   += __shfl_down_sync(0xFFFFFFFFu, sk,   off);
            sc   += __shfl_down_sync(0xFFFFFFFFu, sc,   off);
            scm  += __shfl_down_sync(0xFFFFFFFFu, scm,  off);
            spe  += __shfl_down_sync(0xFFFFFFFFu, spe,  off);
            snp  += __shfl_down_sync(0xFFFFFFFFu, snp,  off);
            sco  += __shfl_down_sync(0xFFFFFFFFu, sco,  off);
            sgt2 += __shfl_down_sync(0xFFFFFFFFu, sgt2, off);
        }
        const int wid = tid >> 5;
        if ((tid & 31) == 0) {
            s_red[wid]      = sp;  s_red[4 + wid]  = sk;
            s_red[8 + wid]  = sc;  s_red[12 + wid] = scm;
            S[wid] = spe; S[4 + wid] = snp; S[8 + wid] = sco; S[12 + wid] = sgt2;
        }
        __syncthreads();
        if (tid == 0) {
            float t0=0,t1=0,t2=0,t3=0,t4=0,t5=0,t6=0,t7=0;
            for (int w = 0; w < 4; w++) {
                t0 += s_red[w]; t1 += s_red[4+w]; t2 += s_red[8+w]; t3 += s_red[12+w];
                t4 += S[w];     t5 += S[4+w];     t6 += S[8+w];     t7 += S[12+w];
            }
            double param_loss  = (double)t0 / 64.0;
            double KLD         = -0.5 * (double)t1 / 64.0 * 10.0;
            double recon_loss  = (double)t2 / 64.0;
            double cmap_loss   = 3000.0 * (double)t3 / (64.0 * (double)t5);
            double consistency = -5.0 * (double)t6 / ((double)t7 + 0.0001);
            double penetr      = 100.0 * (double)t4 / 64.0;
            double loss = (recon_loss + KLD) + 0.1 * param_loss
                        + 1000.0 * cmap_loss + 10.0 * consistency + 10.0 * penetr;
            out[0] = (float)loss;
        }
        for (int i = tid; i < BN; i += TPB) g_bdone[i] = 0;
        __syncthreads();
        if (tid == 0) { g_ticket = 0; g_fin = 0; __threadfence(); }
    }
}

extern "C" void kernel_launch(void* const* d_in, const int* in_sizes, int n_in,
                              void* d_out, int out_size) {
    const float* obj   = (const float*)d_in[0];
    const float* recon = (const float*)d_in[1];
    const float* gt    = (const float*)d_in[2];
    const float* mean  = (const float*)d_in[3];
    const float* logv  = (const float*)d_in[4];
    const float* rp    = (const float*)d_in[5];
    const float* xp    = (const float*)d_in[6];
    const int*   faces = (const int*)d_in[7];
    float* out = (float*)d_out;

    k_mega<<<NBLOCKS, TPB>>>(obj, recon, gt, faces, mean, logv, rp, xp, out);
}